// round 1
// baseline (speedup 1.0000x reference)
#include <cuda_runtime.h>
#include <math.h>

// Problem dims (fixed by the dataset)
#define DFEAT 256          // per-table feature dim
#define KDIM  512          // concat dim = 2*DFEAT
#define H     128
#define H2    64
#define NC    192          // H + H2 fused output cols of stage 1
#define MT    64           // edges per block
#define KC    32           // k-chunk
#define THREADS 256
#define XPAD  36           // padded x row (floats), 36*4=144B keeps float4 alignment

// Dynamic smem layout (floats):
//  [0 .. 2304)            x_s[MT][XPAD]            (phase 1)   -- aliased by w2_s[H][H2]=8192 in phase 2
//  [2304 .. 8448)         w_s[KC][NC]              (phase 1)
//  [8448 .. 20736)        hbuf[MT][NC]
//  [20736 .. 24832)       h2buf[MT][H2]
//  [24832 .. 24960)       ridx[2][MT] (ints)
#define SM_XS    0
#define SM_WS    2304
#define SM_HBUF  8448
#define SM_H2BUF 20736
#define SM_RIDX  24832
#define SM_FLOATS 24960
#define SM_BYTES (SM_FLOATS * 4)

__device__ __forceinline__ float gelu_exact(float x) {
    return 0.5f * x * (1.0f + erff(x * 0.70710678118654752440f));
}

__global__ void __launch_bounds__(THREADS, 2)
mlp_decoder_kernel(const float* __restrict__ drug, const float* __restrict__ dis,
                   const int* __restrict__ src, const int* __restrict__ dst,
                   const float* __restrict__ W1, const float* __restrict__ b1,
                   const float* __restrict__ g1, const float* __restrict__ be1,
                   const float* __restrict__ W2, const float* __restrict__ b2,
                   const float* __restrict__ g2, const float* __restrict__ be2,
                   const float* __restrict__ W3, const float* __restrict__ b3,
                   const float* __restrict__ Ws, const float* __restrict__ bs,
                   float* __restrict__ out, int E)
{
    extern __shared__ float sm[];
    float* x_s   = sm + SM_XS;     // [MT][XPAD]
    float* w_s   = sm + SM_WS;     // [KC][NC]
    float* w2_s  = sm + SM_XS;     // [H][H2]  (alias, phase 2)
    float* hbuf  = sm + SM_HBUF;   // [MT][NC]
    float* h2buf = sm + SM_H2BUF;  // [MT][H2]
    int*   ridx  = (int*)(sm + SM_RIDX); // [2][MT]

    const int tid = threadIdx.x;
    const int e0  = blockIdx.x * MT;

    // ---- load edge indices ----
    if (tid < MT) {
        int e = e0 + tid;
        ridx[tid]      = (e < E) ? src[e] : 0;
        ridx[MT + tid] = (e < E) ? dst[e] : 0;
    }

    // GEMM1+shortcut thread tile: 4 rows x 12 cols
    const int tr = tid >> 4;          // 0..15
    const int tc = tid & 15;          // 0..15
    const int r0 = tr * 4;
    const int c0 = tc * 12;

    float acc[4][12];
    #pragma unroll
    for (int i = 0; i < 4; ++i)
        #pragma unroll
        for (int j = 0; j < 12; ++j) acc[i][j] = 0.0f;

    // ---- fused GEMM1 ([MT,512]x[512,128]) + shortcut ([MT,512]x[512,64]) ----
    for (int kc = 0; kc < KDIM / KC; ++kc) {
        const int k0 = kc * KC;
        __syncthreads();  // prior chunk consumed (also covers ridx on iter 0)

        // stage gathered x chunk: [MT][KC] -> x_s[row][k]
        {
            const float* tab = (k0 < DFEAT) ? drug : dis;
            const int koff   = (k0 < DFEAT) ? k0 : (k0 - DFEAT);
            const int tsel   = (k0 < DFEAT) ? 0 : 1;
            #pragma unroll
            for (int it = 0; it < 2; ++it) {
                int s   = tid + it * THREADS;   // 0..511 float4 slots
                int row = s >> 3;
                int k4  = (s & 7) << 2;
                int idx = ridx[tsel * MT + row];
                float4 v = *(const float4*)(tab + (long)idx * DFEAT + koff + k4);
                *(float4*)(x_s + row * XPAD + k4) = v;
            }
        }
        // stage W chunk: w_s[k][0..127] = W1[k0+k][:], w_s[k][128..191] = Ws[k0+k][:]
        {
            #pragma unroll
            for (int it = 0; it < 6; ++it) {
                int s = tid + it * THREADS;     // 0..1535 float4 slots (48 per k-row)
                int k = s / 48;
                int q = s % 48;
                float4 v;
                if (q < 32) v = *(const float4*)(W1 + (long)(k0 + k) * H  + q * 4);
                else        v = *(const float4*)(Ws + (long)(k0 + k) * H2 + (q - 32) * 4);
                *(float4*)(w_s + k * NC + q * 4) = v;
            }
        }
        __syncthreads();

        #pragma unroll 8
        for (int k = 0; k < KC; ++k) {
            float a[4];
            #pragma unroll
            for (int i = 0; i < 4; ++i) a[i] = x_s[(r0 + i) * XPAD + k];
            float b[12];
            #pragma unroll
            for (int j = 0; j < 12; j += 4) {
                float4 w4 = *(const float4*)(w_s + k * NC + c0 + j);
                b[j] = w4.x; b[j+1] = w4.y; b[j+2] = w4.z; b[j+3] = w4.w;
            }
            #pragma unroll
            for (int i = 0; i < 4; ++i)
                #pragma unroll
                for (int j = 0; j < 12; ++j)
                    acc[i][j] = fmaf(a[i], b[j], acc[i][j]);
        }
    }
    __syncthreads();

    // write stage-1 result with bias: cols [0,H) = x@W1+b1 ; [H,NC) = x@Ws+bs
    #pragma unroll
    for (int i = 0; i < 4; ++i) {
        #pragma unroll
        for (int j = 0; j < 12; ++j) {
            int c = c0 + j;
            float bias = (c < H) ? b1[c] : bs[c - H];
            hbuf[(r0 + i) * NC + c] = acc[i][j] + bias;
        }
    }
    __syncthreads();

    // ---- LayerNorm(H) + exact GELU, in place on hbuf[:, 0:H) ----
    const int wid  = tid >> 5;
    const int lane = tid & 31;
    for (int rr = 0; rr < 8; ++rr) {
        int row = wid * 8 + rr;
        float v[4], s = 0.0f, ss = 0.0f;
        #pragma unroll
        for (int i = 0; i < 4; ++i) {
            v[i] = hbuf[row * NC + lane + 32 * i];
            s += v[i]; ss += v[i] * v[i];
        }
        #pragma unroll
        for (int o = 16; o > 0; o >>= 1) {
            s  += __shfl_xor_sync(0xffffffffu, s,  o);
            ss += __shfl_xor_sync(0xffffffffu, ss, o);
        }
        float mu   = s * (1.0f / H);
        float var  = ss * (1.0f / H) - mu * mu;
        float rstd = rsqrtf(var + 1e-5f);
        #pragma unroll
        for (int i = 0; i < 4; ++i) {
            int c = lane + 32 * i;
            float y = (v[i] - mu) * rstd * g1[c] + be1[c];
            hbuf[row * NC + c] = gelu_exact(y);
        }
    }
    __syncthreads();

    // ---- stage W2 [H][H2] into w2_s (aliases x_s/w_s region) ----
    #pragma unroll
    for (int it = 0; it < 8; ++it) {
        int s = tid + it * THREADS;   // 2048 float4 slots
        *(float4*)(w2_s + s * 4) = *(const float4*)(W2 + s * 4);
    }
    __syncthreads();

    // ---- GEMM2: [MT,H] x [H,H2], thread tile 4x4 ----
    {
        const int c02 = tc * 4;
        float acc2[4][4];
        #pragma unroll
        for (int i = 0; i < 4; ++i)
            #pragma unroll
            for (int j = 0; j < 4; ++j) acc2[i][j] = 0.0f;

        #pragma unroll 8
        for (int k = 0; k < H; ++k) {
            float a[4];
            #pragma unroll
            for (int i = 0; i < 4; ++i) a[i] = hbuf[(r0 + i) * NC + k];
            float4 w4 = *(const float4*)(w2_s + k * H2 + c02);
            float b4[4] = {w4.x, w4.y, w4.z, w4.w};
            #pragma unroll
            for (int i = 0; i < 4; ++i)
                #pragma unroll
                for (int j = 0; j < 4; ++j)
                    acc2[i][j] = fmaf(a[i], b4[j], acc2[i][j]);
        }
        #pragma unroll
        for (int i = 0; i < 4; ++i)
            #pragma unroll
            for (int j = 0; j < 4; ++j)
                h2buf[(r0 + i) * H2 + c02 + j] = acc2[i][j] + b2[c02 + j];
    }
    __syncthreads();

    // ---- LN(H2) + identity + GELU + dot(W3) + b3 ----
    for (int rr = 0; rr < 8; ++rr) {
        int row = wid * 8 + rr;
        float v0 = h2buf[row * H2 + lane];
        float v1 = h2buf[row * H2 + lane + 32];
        float s = v0 + v1, ss = v0 * v0 + v1 * v1;
        #pragma unroll
        for (int o = 16; o > 0; o >>= 1) {
            s  += __shfl_xor_sync(0xffffffffu, s,  o);
            ss += __shfl_xor_sync(0xffffffffu, ss, o);
        }
        float mu   = s * (1.0f / H2);
        float var  = ss * (1.0f / H2) - mu * mu;
        float rstd = rsqrtf(var + 1e-5f);

        float y0 = (v0 - mu) * rstd * g2[lane]      + be2[lane];
        float y1 = (v1 - mu) * rstd * g2[lane + 32] + be2[lane + 32];
        // identity (x@Ws + bs) already has bias folded in hbuf cols [H,NC)
        float h0 = gelu_exact(y0 + hbuf[row * NC + H + lane]);
        float h1 = gelu_exact(y1 + hbuf[row * NC + H + lane + 32]);
        float r  = h0 * W3[lane] + h1 * W3[lane + 32];
        #pragma unroll
        for (int o = 16; o > 0; o >>= 1)
            r += __shfl_xor_sync(0xffffffffu, r, o);
        if (lane == 0 && (e0 + row) < E)
            out[e0 + row] = r + b3[0];
    }
}

extern "C" void kernel_launch(void* const* d_in, const int* in_sizes, int n_in,
                              void* d_out, int out_size) {
    const float* drug = (const float*)d_in[0];
    const float* dis  = (const float*)d_in[1];
    const int*   src  = (const int*)  d_in[2];
    const int*   dst  = (const int*)  d_in[3];
    const float* W1   = (const float*)d_in[4];
    const float* b1   = (const float*)d_in[5];
    const float* g1   = (const float*)d_in[6];
    const float* be1  = (const float*)d_in[7];
    const float* W2   = (const float*)d_in[8];
    const float* b2   = (const float*)d_in[9];
    const float* g2   = (const float*)d_in[10];
    const float* be2  = (const float*)d_in[11];
    const float* W3   = (const float*)d_in[12];
    const float* b3   = (const float*)d_in[13];
    const float* Ws   = (const float*)d_in[14];
    const float* bs   = (const float*)d_in[15];

    const int E = in_sizes[2];
    cudaFuncSetAttribute(mlp_decoder_kernel,
                         cudaFuncAttributeMaxDynamicSharedMemorySize, SM_BYTES);
    const int grid = (E + MT - 1) / MT;
    mlp_decoder_kernel<<<grid, THREADS, SM_BYTES>>>(
        drug, dis, src, dst, W1, b1, g1, be1, W2, b2, g2, be2, W3, b3, Ws, bs,
        (float*)d_out, E);
}

// round 3
// speedup vs baseline: 2.3776x; 2.3776x over previous
#include <cuda_runtime.h>
#include <cuda_bf16.h>
#include <math.h>
#include <stdint.h>

// ---------------- problem dims ----------------
#define DFEAT 256
#define KDIM  512
#define H     128
#define H2    64
#define NC1   192          // fused stage-1 output cols (W1 | Ws)
#define MTILE 128          // edges per CTA
#define KC    64           // K-chunk
#define THREADS 512        // 16 warps: 4 m-warps x 4 n-warps

// ---------------- smem layout (bytes) ----------------
#define OFF_PS   0          // [128][4] float row partial sums
#define OFF_PQ   2048       // [128][4] float row partial sumsq
#define OFF_MU   4096       // [128] float
#define OFF_RS   4608       // [128] float
#define OFF_RIDX 5120       // int[256]
#define OFF_ID   6144       // [128][64] float identity buffer (ends 38912)
// phase 1 (A pitch 144B = 64 bf16 + 8 pad; B pitch 144B)
#define OFF_A1HI 38912      // 128*144 = 18432
#define OFF_A1LO 57344
#define OFF_B1HI 75776      // 192*144 = 27648
#define OFF_B1LO 103424     // ends 131072
// phase 2 (aliases phase 1; pitch 272B = 128 bf16 + 8 pad)
#define OFF_A2HI 38912      // 128*272 = 34816
#define OFF_A2LO 73728
#define OFF_B2HI 108544     // 64*272 = 17408
#define OFF_B2LO 125952     // ends 143360
#define SMEM_BYTES 143360

// ---------------- prepped split weights ----------------
__device__ __align__(16) __nv_bfloat16 g_WcatT_hi[NC1 * KDIM];  // [n][k]
__device__ __align__(16) __nv_bfloat16 g_WcatT_lo[NC1 * KDIM];
__device__ __align__(16) __nv_bfloat16 g_W2T_hi[H2 * H];        // [n][k]
__device__ __align__(16) __nv_bfloat16 g_W2T_lo[H2 * H];

// ---------------- helpers ----------------
__device__ __forceinline__ uint32_t smem_u32(const void* p) {
    uint32_t a;
    asm("{ .reg .u64 t; cvta.to.shared.u64 t, %1; cvt.u32.u64 %0, t; }" : "=r"(a) : "l"(p));
    return a;
}
__device__ __forceinline__ void ldsm_x4(uint32_t addr, uint32_t* r) {
    asm volatile("ldmatrix.sync.aligned.m8n8.x4.shared.b16 {%0,%1,%2,%3}, [%4];"
        : "=r"(r[0]), "=r"(r[1]), "=r"(r[2]), "=r"(r[3]) : "r"(addr));
}
__device__ __forceinline__ void mma_bf16(float* d, const uint32_t* a, const uint32_t* b) {
    asm volatile(
        "mma.sync.aligned.m16n8k16.row.col.f32.bf16.bf16.f32 "
        "{%0,%1,%2,%3}, {%4,%5,%6,%7}, {%8,%9}, {%0,%1,%2,%3};"
        : "+f"(d[0]), "+f"(d[1]), "+f"(d[2]), "+f"(d[3])
        : "r"(a[0]), "r"(a[1]), "r"(a[2]), "r"(a[3]), "r"(b[0]), "r"(b[1]));
}
__device__ __forceinline__ uint32_t pack_bf16(__nv_bfloat16 a, __nv_bfloat16 b) {
    return (uint32_t)__bfloat16_as_ushort(a) | ((uint32_t)__bfloat16_as_ushort(b) << 16);
}
__device__ __forceinline__ void split2(float f, __nv_bfloat16& h, __nv_bfloat16& l) {
    h = __float2bfloat16(f);
    l = __float2bfloat16(f - __bfloat162float(h));
}
__device__ __forceinline__ float gelu_exact(float x) {
    return 0.5f * x * (1.0f + erff(x * 0.70710678118654752440f));
}

// ---------------- prep kernel: split + transpose weights ----------------
__global__ void prep_weights(const float* __restrict__ W1, const float* __restrict__ Ws,
                             const float* __restrict__ W2) {
    int i = blockIdx.x * 256 + threadIdx.x;
    if (i < NC1 * KDIM) {
        int n = i / KDIM, k = i % KDIM;
        float w = (n < H) ? W1[k * H + n] : Ws[k * H2 + (n - H)];
        __nv_bfloat16 h, l; split2(w, h, l);
        g_WcatT_hi[i] = h; g_WcatT_lo[i] = l;
    } else {
        int j = i - NC1 * KDIM;
        if (j < H2 * H) {
            int n = j / H, k = j % H;
            float w = W2[k * H2 + n];
            __nv_bfloat16 h, l; split2(w, h, l);
            g_W2T_hi[j] = h; g_W2T_lo[j] = l;
        }
    }
}

// ---------------- main kernel ----------------
__global__ void __launch_bounds__(THREADS, 1)
mlp_hmma_kernel(const float* __restrict__ drug, const float* __restrict__ dis,
                const int* __restrict__ src, const int* __restrict__ dst,
                const float* __restrict__ b1, const float* __restrict__ g1,
                const float* __restrict__ be1,
                const float* __restrict__ b2, const float* __restrict__ g2,
                const float* __restrict__ be2,
                const float* __restrict__ W3, const float* __restrict__ b3,
                const float* __restrict__ bs,
                float* __restrict__ out, int E)
{
    extern __shared__ char smem[];
    const uint32_t sb = smem_u32(smem);
    const int tid = threadIdx.x, wid = tid >> 5, lane = tid & 31;
    const int e0 = blockIdx.x * MTILE;

    float* psum = (float*)(smem + OFF_PS);   // [128][4]
    float* psq  = (float*)(smem + OFF_PQ);   // [128][4]
    float* mu_s = (float*)(smem + OFF_MU);
    float* rs_s = (float*)(smem + OFF_RS);
    int*   ridx = (int*)(smem + OFF_RIDX);
    float* idbf = (float*)(smem + OFF_ID);   // [128][64]

    if (tid < MTILE) {
        int e = e0 + tid;
        ridx[tid]         = (e < E) ? src[e] : 0;
        ridx[MTILE + tid] = (e < E) ? dst[e] : 0;
    }

    // warp tiling
    const int mw = wid >> 2, nw = wid & 3;
    const int m0 = mw * 32;            // 32 rows per m-warp
    const int n0 = nw * 48;            // 48 cols per n-warp (stage 1)
    const int lrow = lane & 15;        // ldmatrix A row-in-tile
    const int kcol = (lane >> 4) * 8;  // ldmatrix A k-offset
    const int brow = (lane & 7) + ((lane >> 4) * 8);   // ldmatrix B n-in-tile
    const int bcol = ((lane >> 3) & 1) * 8;            // ldmatrix B k-offset
    const int qr = lane >> 2;          // 0..7 (row within 8)
    const int qc = (lane & 3) * 2;     // col pair within n8

    // ldmatrix base addresses (stage 1)
    const uint32_t aHi = sb + OFF_A1HI + (m0 + lrow) * 144 + kcol * 2;
    const uint32_t aLo = sb + OFF_A1LO + (m0 + lrow) * 144 + kcol * 2;
    const uint32_t bHi = sb + OFF_B1HI + (n0 + brow) * 144 + bcol * 2;
    const uint32_t bLo = sb + OFF_B1LO + (n0 + brow) * 144 + bcol * 2;

    float acc[2][6][4];
    #pragma unroll
    for (int mi = 0; mi < 2; ++mi)
        #pragma unroll
        for (int ni = 0; ni < 6; ++ni)
            #pragma unroll
            for (int j = 0; j < 4; ++j) acc[mi][ni][j] = 0.0f;

    // ================= stage 1: [128,512] x [512,192], 8 K-chunks =================
    for (int c = 0; c < 8; ++c) {
        __syncthreads();   // prior chunk consumed (iter 0: ridx visible)

        // --- gather + split A chunk: 128 rows x 64 cols ---
        {
            const float* tab = (c < 4) ? drug : dis;
            const int koff = (c & 3) * KC;
            const int row = tid >> 2, q = tid & 3;
            const long idx = (long)ridx[((c < 4) ? 0 : MTILE) + row];
            const float* sp = tab + idx * DFEAT + koff + q * 16;
            char* dh = smem + OFF_A1HI + row * 144 + q * 32;
            char* dl = smem + OFF_A1LO + row * 144 + q * 32;
            #pragma unroll
            for (int j = 0; j < 4; ++j) {
                float4 v = *(const float4*)(sp + 4 * j);
                __nv_bfloat16 h0,h1,h2,h3,l0,l1,l2,l3;
                split2(v.x, h0, l0); split2(v.y, h1, l1);
                split2(v.z, h2, l2); split2(v.w, h3, l3);
                *(uint2*)(dh + j * 8) = make_uint2(pack_bf16(h0,h1), pack_bf16(h2,h3));
                *(uint2*)(dl + j * 8) = make_uint2(pack_bf16(l0,l1), pack_bf16(l2,l3));
            }
        }
        // --- stage B chunk: 192 rows x 64 cols, hi & lo ---
        #pragma unroll
        for (int it = 0; it < 6; ++it) {
            int s = tid + it * THREADS;            // 0..3071
            int buf = (s >= 1536);
            int t2 = s - buf * 1536;
            int n = t2 >> 3, j = t2 & 7;
            const char* srcp = (buf ? (const char*)g_WcatT_lo : (const char*)g_WcatT_hi)
                               + n * 1024 + c * 128 + j * 16;
            *(uint4*)(smem + (buf ? OFF_B1LO : OFF_B1HI) + n * 144 + j * 16) =
                *(const uint4*)srcp;
        }
        __syncthreads();

        // --- MMA: 4 k16 steps, 3 passes each ---
        #pragma unroll
        for (int ks = 0; ks < 4; ++ks) {
            const uint32_t ko = ks * 32;   // k0*2 bytes
            uint32_t ah[2][4], bh[3][4];
            #pragma unroll
            for (int mi = 0; mi < 2; ++mi) ldsm_x4(aHi + mi * 2304 + ko, ah[mi]);
            #pragma unroll
            for (int p = 0; p < 3; ++p)    ldsm_x4(bHi + p * 2304 + ko, bh[p]);
            #pragma unroll
            for (int mi = 0; mi < 2; ++mi)
                #pragma unroll
                for (int ni = 0; ni < 6; ++ni)
                    mma_bf16(acc[mi][ni], ah[mi], &bh[ni >> 1][(ni & 1) * 2]);
            {
                uint32_t al[2][4];
                #pragma unroll
                for (int mi = 0; mi < 2; ++mi) ldsm_x4(aLo + mi * 2304 + ko, al[mi]);
                #pragma unroll
                for (int mi = 0; mi < 2; ++mi)
                    #pragma unroll
                    for (int ni = 0; ni < 6; ++ni)
                        mma_bf16(acc[mi][ni], al[mi], &bh[ni >> 1][(ni & 1) * 2]);
            }
            {
                uint32_t bl[3][4];
                #pragma unroll
                for (int p = 0; p < 3; ++p) ldsm_x4(bLo + p * 2304 + ko, bl[p]);
                #pragma unroll
                for (int mi = 0; mi < 2; ++mi)
                    #pragma unroll
                    for (int ni = 0; ni < 6; ++ni)
                        mma_bf16(acc[mi][ni], ah[mi], &bl[ni >> 1][(ni & 1) * 2]);
            }
        }
    }
    __syncthreads();

    // ================= epilogue 1: bias, LN(128), GELU, split -> A2; identity -> idbf ====
    // add biases
    #pragma unroll
    for (int mi = 0; mi < 2; ++mi)
        #pragma unroll
        for (int ni = 0; ni < 6; ++ni) {
            int cc = n0 + ni * 8 + qc;
            float2 bv = (cc < H) ? *(const float2*)(b1 + cc)
                                 : *(const float2*)(bs + cc - H);
            acc[mi][ni][0] += bv.x; acc[mi][ni][1] += bv.y;
            acc[mi][ni][2] += bv.x; acc[mi][ni][3] += bv.y;
        }

    // LN partial sums over cols < 128 owned by this warp
    {
        const int nLim = (nw < 2) ? 6 : ((nw == 2) ? 4 : 0);
        float s[4] = {0,0,0,0}, q[4] = {0,0,0,0};
        for (int mi = 0; mi < 2; ++mi)
            for (int ni = 0; ni < nLim; ++ni) {
                s[mi*2+0] += acc[mi][ni][0] + acc[mi][ni][1];
                q[mi*2+0] += acc[mi][ni][0]*acc[mi][ni][0] + acc[mi][ni][1]*acc[mi][ni][1];
                s[mi*2+1] += acc[mi][ni][2] + acc[mi][ni][3];
                q[mi*2+1] += acc[mi][ni][2]*acc[mi][ni][2] + acc[mi][ni][3]*acc[mi][ni][3];
            }
        #pragma unroll
        for (int i = 0; i < 4; ++i) {
            s[i] += __shfl_xor_sync(0xffffffffu, s[i], 1);
            s[i] += __shfl_xor_sync(0xffffffffu, s[i], 2);
            q[i] += __shfl_xor_sync(0xffffffffu, q[i], 1);
            q[i] += __shfl_xor_sync(0xffffffffu, q[i], 2);
        }
        if ((lane & 3) == 0 && nw < 3) {
            #pragma unroll
            for (int i = 0; i < 4; ++i) {
                int r = m0 + qr + ((i & 1) ? 8 : 0) + ((i >> 1) ? 16 : 0);
                psum[r * 4 + nw] = s[i];
                psq [r * 4 + nw] = q[i];
            }
        }
    }
    __syncthreads();
    if (tid < MTILE) {
        float S = psum[tid*4] + psum[tid*4+1] + psum[tid*4+2];
        float Q = psq [tid*4] + psq [tid*4+1] + psq [tid*4+2];
        float mu = S * (1.0f / H);
        mu_s[tid] = mu;
        rs_s[tid] = rsqrtf(Q * (1.0f / H) - mu * mu + 1e-5f);
    }
    __syncthreads();

    {
        int rows[4];
        float muv[4], rsv[4];
        #pragma unroll
        for (int i = 0; i < 4; ++i) {
            rows[i] = m0 + qr + ((i & 1) ? 8 : 0) + ((i >> 1) ? 16 : 0);
            muv[i] = mu_s[rows[i]];
            rsv[i] = rs_s[rows[i]];
        }
        #pragma unroll
        for (int mi = 0; mi < 2; ++mi)
            #pragma unroll
            for (int ni = 0; ni < 6; ++ni) {
                int cc = n0 + ni * 8 + qc;
                if (cc < H) {
                    float2 gv = *(const float2*)(g1 + cc);
                    float2 bev = *(const float2*)(be1 + cc);
                    #pragma unroll
                    for (int half = 0; half < 2; ++half) {
                        int i = mi * 2 + half, r = rows[i];
                        float y0 = (acc[mi][ni][half*2]   - muv[i]) * rsv[i] * gv.x + bev.x;
                        float y1 = (acc[mi][ni][half*2+1] - muv[i]) * rsv[i] * gv.y + bev.y;
                        float h0 = gelu_exact(y0), h1 = gelu_exact(y1);
                        __nv_bfloat16 hh0,ll0,hh1,ll1;
                        split2(h0, hh0, ll0); split2(h1, hh1, ll1);
                        *(uint32_t*)(smem + OFF_A2HI + r * 272 + cc * 2) = pack_bf16(hh0, hh1);
                        *(uint32_t*)(smem + OFF_A2LO + r * 272 + cc * 2) = pack_bf16(ll0, ll1);
                    }
                } else {
                    #pragma unroll
                    for (int half = 0; half < 2; ++half) {
                        int i = mi * 2 + half, r = rows[i];
                        *(float2*)(idbf + r * 64 + (cc - H)) =
                            make_float2(acc[mi][ni][half*2], acc[mi][ni][half*2+1]);
                    }
                }
            }
    }
    __syncthreads();

    // --- stage B2: [64][128] hi & lo -> pitch 272 ---
    #pragma unroll
    for (int it = 0; it < 4; ++it) {
        int s = tid + it * THREADS;        // 0..2047
        int buf = (s >= 1024);
        int t2 = s - buf * 1024;
        int n = t2 >> 4, j = t2 & 15;
        const char* srcp = (buf ? (const char*)g_W2T_lo : (const char*)g_W2T_hi)
                           + n * 256 + j * 16;
        *(uint4*)(smem + (buf ? OFF_B2LO : OFF_B2HI) + n * 272 + j * 16) =
            *(const uint4*)srcp;
    }
    __syncthreads();

    // ================= stage 2: [128,128] x [128,64] =================
    float ac2[2][2][4];
    #pragma unroll
    for (int mi = 0; mi < 2; ++mi)
        #pragma unroll
        for (int ni = 0; ni < 2; ++ni)
            #pragma unroll
            for (int j = 0; j < 4; ++j) ac2[mi][ni][j] = 0.0f;

    {
        const uint32_t a2Hi = sb + OFF_A2HI + (m0 + lrow) * 272 + kcol * 2;
        const uint32_t a2Lo = sb + OFF_A2LO + (m0 + lrow) * 272 + kcol * 2;
        const uint32_t b2Hi = sb + OFF_B2HI + (nw * 16 + brow) * 272 + bcol * 2;
        const uint32_t b2Lo = sb + OFF_B2LO + (nw * 16 + brow) * 272 + bcol * 2;
        #pragma unroll
        for (int ks = 0; ks < 8; ++ks) {
            const uint32_t ko = ks * 32;
            uint32_t ah[2][4], bh[4], al[2][4], bl[4];
            #pragma unroll
            for (int mi = 0; mi < 2; ++mi) ldsm_x4(a2Hi + mi * 4352 + ko, ah[mi]);
            ldsm_x4(b2Hi + ko, bh);
            #pragma unroll
            for (int mi = 0; mi < 2; ++mi)
                #pragma unroll
                for (int ni = 0; ni < 2; ++ni)
                    mma_bf16(ac2[mi][ni], ah[mi], &bh[ni * 2]);
            #pragma unroll
            for (int mi = 0; mi < 2; ++mi) ldsm_x4(a2Lo + mi * 4352 + ko, al[mi]);
            #pragma unroll
            for (int mi = 0; mi < 2; ++mi)
                #pragma unroll
                for (int ni = 0; ni < 2; ++ni)
                    mma_bf16(ac2[mi][ni], al[mi], &bh[ni * 2]);
            ldsm_x4(b2Lo + ko, bl);
            #pragma unroll
            for (int mi = 0; mi < 2; ++mi)
                #pragma unroll
                for (int ni = 0; ni < 2; ++ni)
                    mma_bf16(ac2[mi][ni], ah[mi], &bl[ni * 2]);
        }
    }
    __syncthreads();

    // ================= epilogue 2: bias, LN(64), +identity, GELU, dot W3 ============
    #pragma unroll
    for (int mi = 0; mi < 2; ++mi)
        #pragma unroll
        for (int ni = 0; ni < 2; ++ni) {
            int cc = nw * 16 + ni * 8 + qc;
            float2 bv = *(const float2*)(b2 + cc);
            ac2[mi][ni][0] += bv.x; ac2[mi][ni][1] += bv.y;
            ac2[mi][ni][2] += bv.x; ac2[mi][ni][3] += bv.y;
        }
    {
        float s[4] = {0,0,0,0}, q[4] = {0,0,0,0};
        #pragma unroll
        for (int mi = 0; mi < 2; ++mi)
            #pragma unroll
            for (int ni = 0; ni < 2; ++ni) {
                s[mi*2+0] += ac2[mi][ni][0] + ac2[mi][ni][1];
                q[mi*2+0] += ac2[mi][ni][0]*ac2[mi][ni][0] + ac2[mi][ni][1]*ac2[mi][ni][1];
                s[mi*2+1] += ac2[mi][ni][2] + ac2[mi][ni][3];
                q[mi*2+1] += ac2[mi][ni][2]*ac2[mi][ni][2] + ac2[mi][ni][3]*ac2[mi][ni][3];
            }
        #pragma unroll
        for (int i = 0; i < 4; ++i) {
            s[i] += __shfl_xor_sync(0xffffffffu, s[i], 1);
            s[i] += __shfl_xor_sync(0xffffffffu, s[i], 2);
            q[i] += __shfl_xor_sync(0xffffffffu, q[i], 1);
            q[i] += __shfl_xor_sync(0xffffffffu, q[i], 2);
        }
        if ((lane & 3) == 0) {
            #pragma unroll
            for (int i = 0; i < 4; ++i) {
                int r = m0 + qr + ((i & 1) ? 8 : 0) + ((i >> 1) ? 16 : 0);
                psum[r * 4 + nw] = s[i];
                psq [r * 4 + nw] = q[i];
            }
        }
    }
    __syncthreads();
    if (tid < MTILE) {
        float S = psum[tid*4] + psum[tid*4+1] + psum[tid*4+2] + psum[tid*4+3];
        float Q = psq [tid*4] + psq [tid*4+1] + psq [tid*4+2] + psq [tid*4+3];
        float mu = S * (1.0f / H2);
        mu_s[tid] = mu;
        rs_s[tid] = rsqrtf(Q * (1.0f / H2) - mu * mu + 1e-5f);
    }
    __syncthreads();
    {
        int rows[4];
        float muv[4], rsv[4], dotp[4] = {0,0,0,0};
        #pragma unroll
        for (int i = 0; i < 4; ++i) {
            rows[i] = m0 + qr + ((i & 1) ? 8 : 0) + ((i >> 1) ? 16 : 0);
            muv[i] = mu_s[rows[i]];
            rsv[i] = rs_s[rows[i]];
        }
        #pragma unroll
        for (int mi = 0; mi < 2; ++mi)
            #pragma unroll
            for (int ni = 0; ni < 2; ++ni) {
                int cc = nw * 16 + ni * 8 + qc;
                float2 gv = *(const float2*)(g2 + cc);
                float2 bev = *(const float2*)(be2 + cc);
                float2 wv = *(const float2*)(W3 + cc);
                #pragma unroll
                for (int half = 0; half < 2; ++half) {
                    int i = mi * 2 + half, r = rows[i];
                    float2 idv = *(const float2*)(idbf + r * 64 + cc);
                    float y0 = (ac2[mi][ni][half*2]   - muv[i]) * rsv[i] * gv.x + bev.x;
                    float y1 = (ac2[mi][ni][half*2+1] - muv[i]) * rsv[i] * gv.y + bev.y;
                    float h0 = gelu_exact(y0 + idv.x);
                    float h1 = gelu_exact(y1 + idv.y);
                    dotp[i] += h0 * wv.x + h1 * wv.y;
                }
            }
        #pragma unroll
        for (int i = 0; i < 4; ++i) {
            dotp[i] += __shfl_xor_sync(0xffffffffu, dotp[i], 1);
            dotp[i] += __shfl_xor_sync(0xffffffffu, dotp[i], 2);
        }
        __syncthreads();   // psum free for reuse as dot partials
        if ((lane & 3) == 0) {
            #pragma unroll
            for (int i = 0; i < 4; ++i)
                psum[rows[i] * 4 + nw] = dotp[i];
        }
    }
    __syncthreads();
    if (tid < MTILE && (e0 + tid) < E) {
        out[e0 + tid] = psum[tid*4] + psum[tid*4+1] + psum[tid*4+2] + psum[tid*4+3]
                        + b3[0];
    }
}

extern "C" void kernel_launch(void* const* d_in, const int* in_sizes, int n_in,
                              void* d_out, int out_size) {
    const float* drug = (const float*)d_in[0];
    const float* dis  = (const float*)d_in[1];
    const int*   src  = (const int*)  d_in[2];
    const int*   dst  = (const int*)  d_in[3];
    const float* W1   = (const float*)d_in[4];
    const float* b1   = (const float*)d_in[5];
    const float* g1   = (const float*)d_in[6];
    const float* be1  = (const float*)d_in[7];
    const float* W2   = (const float*)d_in[8];
    const float* b2   = (const float*)d_in[9];
    const float* g2   = (const float*)d_in[10];
    const float* be2  = (const float*)d_in[11];
    const float* W3   = (const float*)d_in[12];
    const float* b3   = (const float*)d_in[13];
    const float* Ws   = (const float*)d_in[14];
    const float* bs   = (const float*)d_in[15];
    const int E = in_sizes[2];

    prep_weights<<<(NC1 * KDIM + H2 * H + 255) / 256, 256>>>(W1, Ws, W2);

    cudaFuncSetAttribute(mlp_hmma_kernel,
                         cudaFuncAttributeMaxDynamicSharedMemorySize, SMEM_BYTES);
    const int grid = (E + MTILE - 1) / MTILE;
    mlp_hmma_kernel<<<grid, THREADS, SMEM_BYTES>>>(
        drug, dis, src, dst, b1, g1, be1, b2, g2, be2, W3, b3, bs,
        (float*)d_out, E);
}

// round 4
// speedup vs baseline: 2.3995x; 1.0092x over previous
#include <cuda_runtime.h>
#include <cuda_bf16.h>
#include <math.h>
#include <stdint.h>

// ---------------- problem dims ----------------
#define DFEAT 256
#define KDIM  512
#define H     128
#define H2    64
#define NC1   192          // fused stage-1 output cols (W1 | Ws)
#define MTILE 128          // edges per CTA
#define KC    64           // K-chunk
#define THREADS 512        // 16 warps: 4 m-warps x 4 n-warps

// ---------------- smem layout (bytes) ----------------
#define OFF_PS   0          // [128][4] float row partial sums
#define OFF_PQ   2048
#define OFF_MU   4096
#define OFF_RS   4608
#define OFF_RIDX 5120       // int[256]
// double-buffered stage-1 chunk sets (pitch 144B = 64 bf16 + 8 pad)
#define CHUNK0   6144
#define A1HI_R   0          // 128*144 = 18432
#define A1LO_R   18432
#define B1HI_R   36864      // 192*144 = 27648
#define B1LO_R   64512
#define CHUNKSZ  92160      // per buffer set
#define SMEM_BYTES (CHUNK0 + 2 * CHUNKSZ)   // 190464
// phase 2 (aliases chunk buffers; pitch 272B = 128 bf16 + 8 pad)
#define OFF_A2HI 6144       // 128*272 = 34816
#define OFF_A2LO 40960
#define OFF_B2HI 75776      // 64*272 = 17408
#define OFF_B2LO 93184
#define OFF_ID   110592     // [128][64] float identity

// ---------------- prepped split weights ----------------
__device__ __align__(16) __nv_bfloat16 g_WcatT_hi[NC1 * KDIM];  // [n][k]
__device__ __align__(16) __nv_bfloat16 g_WcatT_lo[NC1 * KDIM];
__device__ __align__(16) __nv_bfloat16 g_W2T_hi[H2 * H];        // [n][k]
__device__ __align__(16) __nv_bfloat16 g_W2T_lo[H2 * H];

// ---------------- helpers ----------------
__device__ __forceinline__ uint32_t smem_u32(const void* p) {
    uint32_t a;
    asm("{ .reg .u64 t; cvta.to.shared.u64 t, %1; cvt.u32.u64 %0, t; }" : "=r"(a) : "l"(p));
    return a;
}
__device__ __forceinline__ void ldsm_x4(uint32_t addr, uint32_t* r) {
    asm volatile("ldmatrix.sync.aligned.m8n8.x4.shared.b16 {%0,%1,%2,%3}, [%4];"
        : "=r"(r[0]), "=r"(r[1]), "=r"(r[2]), "=r"(r[3]) : "r"(addr));
}
__device__ __forceinline__ void mma_bf16(float* d, const uint32_t* a, const uint32_t* b) {
    asm volatile(
        "mma.sync.aligned.m16n8k16.row.col.f32.bf16.bf16.f32 "
        "{%0,%1,%2,%3}, {%4,%5,%6,%7}, {%8,%9}, {%0,%1,%2,%3};"
        : "+f"(d[0]), "+f"(d[1]), "+f"(d[2]), "+f"(d[3])
        : "r"(a[0]), "r"(a[1]), "r"(a[2]), "r"(a[3]), "r"(b[0]), "r"(b[1]));
}
__device__ __forceinline__ uint32_t pack_bf16(__nv_bfloat16 a, __nv_bfloat16 b) {
    return (uint32_t)__bfloat16_as_ushort(a) | ((uint32_t)__bfloat16_as_ushort(b) << 16);
}
__device__ __forceinline__ void split2(float f, __nv_bfloat16& h, __nv_bfloat16& l) {
    h = __float2bfloat16(f);
    l = __float2bfloat16(f - __bfloat162float(h));
}
__device__ __forceinline__ float gelu_exact(float x) {
    return 0.5f * x * (1.0f + erff(x * 0.70710678118654752440f));
}

// ---------------- prep kernel: split + transpose weights ----------------
__global__ void prep_weights(const float* __restrict__ W1, const float* __restrict__ Ws,
                             const float* __restrict__ W2) {
    int i = blockIdx.x * 256 + threadIdx.x;
    if (i < NC1 * KDIM) {
        int n = i / KDIM, k = i % KDIM;
        float w = (n < H) ? W1[k * H + n] : Ws[k * H2 + (n - H)];
        __nv_bfloat16 h, l; split2(w, h, l);
        g_WcatT_hi[i] = h; g_WcatT_lo[i] = l;
    } else {
        int j = i - NC1 * KDIM;
        if (j < H2 * H) {
            int n = j / H, k = j % H;
            float w = W2[k * H2 + n];
            __nv_bfloat16 h, l; split2(w, h, l);
            g_W2T_hi[j] = h; g_W2T_lo[j] = l;
        }
    }
}

// ---------------- main kernel ----------------
__global__ void __launch_bounds__(THREADS, 1)
mlp_hmma_kernel(const float* __restrict__ drug, const float* __restrict__ dis,
                const int* __restrict__ src, const int* __restrict__ dst,
                const float* __restrict__ b1, const float* __restrict__ g1,
                const float* __restrict__ be1,
                const float* __restrict__ b2, const float* __restrict__ g2,
                const float* __restrict__ be2,
                const float* __restrict__ W3, const float* __restrict__ b3,
                const float* __restrict__ bs,
                float* __restrict__ out, int E)
{
    extern __shared__ char smem[];
    const uint32_t sb = smem_u32(smem);
    const int tid = threadIdx.x, wid = tid >> 5, lane = tid & 31;
    const int e0 = blockIdx.x * MTILE;

    float* psum = (float*)(smem + OFF_PS);
    float* psq  = (float*)(smem + OFF_PQ);
    float* mu_s = (float*)(smem + OFF_MU);
    float* rs_s = (float*)(smem + OFF_RS);
    int*   ridx = (int*)(smem + OFF_RIDX);
    float* idbf = (float*)(smem + OFF_ID);

    if (tid < MTILE) {
        int e = e0 + tid;
        ridx[tid]         = (e < E) ? src[e] : 0;
        ridx[MTILE + tid] = (e < E) ? dst[e] : 0;
    }
    __syncthreads();

    // warp tiling
    const int mw = wid >> 2, nw = wid & 3;
    const int m0 = mw * 32;
    const int n0 = nw * 48;
    const int lrow = lane & 15;
    const int kcol = (lane >> 4) * 8;
    const int brow = (lane & 7) + ((lane >> 4) * 8);
    const int bcol = ((lane >> 3) & 1) * 8;
    const int qr = lane >> 2;
    const int qc = (lane & 3) * 2;

    const uint32_t aoffA = (m0 + lrow) * 144 + kcol * 2;
    const uint32_t boffB = (n0 + brow) * 144 + bcol * 2;

    // staging coords
    const int grow = tid >> 2, gq = tid & 3;   // A gather: 128 rows x 4 thr

    float acc[2][6][4];
    #pragma unroll
    for (int mi = 0; mi < 2; ++mi)
        #pragma unroll
        for (int ni = 0; ni < 6; ++ni)
            #pragma unroll
            for (int j = 0; j < 4; ++j) acc[mi][ni][j] = 0.0f;

    float4 aReg[4];
    uint4  bReg[6];

    // ---- prefetch helpers (inlined via lambdas) ----
    auto load_chunk = [&](int cc) {
        const float* tab = (cc < 4) ? drug : dis;
        const long idx = (long)ridx[((cc < 4) ? 0 : MTILE) + grow];
        const float* sp = tab + idx * DFEAT + (cc & 3) * KC + gq * 16;
        #pragma unroll
        for (int j = 0; j < 4; ++j) aReg[j] = *(const float4*)(sp + 4 * j);
        #pragma unroll
        for (int it = 0; it < 6; ++it) {
            int s = tid + it * THREADS;
            int half = (s >= 1536);
            int t2 = s - half * 1536;
            int n = t2 >> 3, j = t2 & 7;
            const char* srcp = (half ? (const char*)g_WcatT_lo : (const char*)g_WcatT_hi)
                               + n * 1024 + cc * 128 + j * 16;
            bReg[it] = *(const uint4*)srcp;
        }
    };
    auto store_chunk = [&](int bsel) {
        char* base = smem + CHUNK0 + bsel * CHUNKSZ;
        char* dh = base + A1HI_R + grow * 144 + gq * 32;
        char* dl = base + A1LO_R + grow * 144 + gq * 32;
        #pragma unroll
        for (int j = 0; j < 4; ++j) {
            __nv_bfloat16 h0,h1,h2,h3,l0,l1,l2,l3;
            split2(aReg[j].x, h0, l0); split2(aReg[j].y, h1, l1);
            split2(aReg[j].z, h2, l2); split2(aReg[j].w, h3, l3);
            *(uint2*)(dh + j * 8) = make_uint2(pack_bf16(h0,h1), pack_bf16(h2,h3));
            *(uint2*)(dl + j * 8) = make_uint2(pack_bf16(l0,l1), pack_bf16(l2,l3));
        }
        #pragma unroll
        for (int it = 0; it < 6; ++it) {
            int s = tid + it * THREADS;
            int half = (s >= 1536);
            int t2 = s - half * 1536;
            int n = t2 >> 3, j = t2 & 7;
            *(uint4*)(base + (half ? B1LO_R : B1HI_R) + n * 144 + j * 16) = bReg[it];
        }
    };

    // ================= stage 1: pipelined double-buffered =================
    load_chunk(0);
    store_chunk(0);
    load_chunk(1);
    __syncthreads();

    for (int c = 0; c < 8; ++c) {
        if (c < 7) store_chunk((c + 1) & 1);
        if (c < 6) load_chunk(c + 2);

        const uint32_t cb = sb + CHUNK0 + ((c & 1) ? CHUNKSZ : 0);
        const uint32_t aHi = cb + A1HI_R + aoffA;
        const uint32_t aLo = cb + A1LO_R + aoffA;
        const uint32_t bHi = cb + B1HI_R + boffB;
        const uint32_t bLo = cb + B1LO_R + boffB;

        #pragma unroll
        for (int ks = 0; ks < 4; ++ks) {
            const uint32_t ko = ks * 32;
            uint32_t ah[2][4], bh[3][4];
            #pragma unroll
            for (int mi = 0; mi < 2; ++mi) ldsm_x4(aHi + mi * 2304 + ko, ah[mi]);
            #pragma unroll
            for (int p = 0; p < 3; ++p)    ldsm_x4(bHi + p * 2304 + ko, bh[p]);
            #pragma unroll
            for (int mi = 0; mi < 2; ++mi)
                #pragma unroll
                for (int ni = 0; ni < 6; ++ni)
                    mma_bf16(acc[mi][ni], ah[mi], &bh[ni >> 1][(ni & 1) * 2]);
            {
                uint32_t al[2][4];
                #pragma unroll
                for (int mi = 0; mi < 2; ++mi) ldsm_x4(aLo + mi * 2304 + ko, al[mi]);
                #pragma unroll
                for (int mi = 0; mi < 2; ++mi)
                    #pragma unroll
                    for (int ni = 0; ni < 6; ++ni)
                        mma_bf16(acc[mi][ni], al[mi], &bh[ni >> 1][(ni & 1) * 2]);
            }
            {
                uint32_t bl[3][4];
                #pragma unroll
                for (int p = 0; p < 3; ++p) ldsm_x4(bLo + p * 2304 + ko, bl[p]);
                #pragma unroll
                for (int mi = 0; mi < 2; ++mi)
                    #pragma unroll
                    for (int ni = 0; ni < 6; ++ni)
                        mma_bf16(acc[mi][ni], ah[mi], &bl[ni >> 1][(ni & 1) * 2]);
            }
        }
        __syncthreads();
    }

    // ================= epilogue 1: bias, LN(128), GELU, split -> A2; identity -> idbf ====
    #pragma unroll
    for (int mi = 0; mi < 2; ++mi)
        #pragma unroll
        for (int ni = 0; ni < 6; ++ni) {
            int cc = n0 + ni * 8 + qc;
            float2 bv = (cc < H) ? *(const float2*)(b1 + cc)
                                 : *(const float2*)(bs + cc - H);
            acc[mi][ni][0] += bv.x; acc[mi][ni][1] += bv.y;
            acc[mi][ni][2] += bv.x; acc[mi][ni][3] += bv.y;
        }
    {
        const int nLim = (nw < 2) ? 6 : ((nw == 2) ? 4 : 0);
        float s[4] = {0,0,0,0}, q[4] = {0,0,0,0};
        for (int mi = 0; mi < 2; ++mi)
            for (int ni = 0; ni < nLim; ++ni) {
                s[mi*2+0] += acc[mi][ni][0] + acc[mi][ni][1];
                q[mi*2+0] += acc[mi][ni][0]*acc[mi][ni][0] + acc[mi][ni][1]*acc[mi][ni][1];
                s[mi*2+1] += acc[mi][ni][2] + acc[mi][ni][3];
                q[mi*2+1] += acc[mi][ni][2]*acc[mi][ni][2] + acc[mi][ni][3]*acc[mi][ni][3];
            }
        #pragma unroll
        for (int i = 0; i < 4; ++i) {
            s[i] += __shfl_xor_sync(0xffffffffu, s[i], 1);
            s[i] += __shfl_xor_sync(0xffffffffu, s[i], 2);
            q[i] += __shfl_xor_sync(0xffffffffu, q[i], 1);
            q[i] += __shfl_xor_sync(0xffffffffu, q[i], 2);
        }
        if ((lane & 3) == 0 && nw < 3) {
            #pragma unroll
            for (int i = 0; i < 4; ++i) {
                int r = m0 + qr + ((i & 1) ? 8 : 0) + ((i >> 1) ? 16 : 0);
                psum[r * 4 + nw] = s[i];
                psq [r * 4 + nw] = q[i];
            }
        }
    }
    __syncthreads();
    if (tid < MTILE) {
        float S = psum[tid*4] + psum[tid*4+1] + psum[tid*4+2];
        float Q = psq [tid*4] + psq [tid*4+1] + psq [tid*4+2];
        float mu = S * (1.0f / H);
        mu_s[tid] = mu;
        rs_s[tid] = rsqrtf(Q * (1.0f / H) - mu * mu + 1e-5f);
    }
    __syncthreads();
    {
        int rows[4];
        float muv[4], rsv[4];
        #pragma unroll
        for (int i = 0; i < 4; ++i) {
            rows[i] = m0 + qr + ((i & 1) ? 8 : 0) + ((i >> 1) ? 16 : 0);
            muv[i] = mu_s[rows[i]];
            rsv[i] = rs_s[rows[i]];
        }
        #pragma unroll
        for (int mi = 0; mi < 2; ++mi)
            #pragma unroll
            for (int ni = 0; ni < 6; ++ni) {
                int cc = n0 + ni * 8 + qc;
                if (cc < H) {
                    float2 gv = *(const float2*)(g1 + cc);
                    float2 bev = *(const float2*)(be1 + cc);
                    #pragma unroll
                    for (int half = 0; half < 2; ++half) {
                        int i = mi * 2 + half, r = rows[i];
                        float y0 = (acc[mi][ni][half*2]   - muv[i]) * rsv[i] * gv.x + bev.x;
                        float y1 = (acc[mi][ni][half*2+1] - muv[i]) * rsv[i] * gv.y + bev.y;
                        float h0 = gelu_exact(y0), h1 = gelu_exact(y1);
                        __nv_bfloat16 hh0,ll0,hh1,ll1;
                        split2(h0, hh0, ll0); split2(h1, hh1, ll1);
                        *(uint32_t*)(smem + OFF_A2HI + r * 272 + cc * 2) = pack_bf16(hh0, hh1);
                        *(uint32_t*)(smem + OFF_A2LO + r * 272 + cc * 2) = pack_bf16(ll0, ll1);
                    }
                } else {
                    #pragma unroll
                    for (int half = 0; half < 2; ++half) {
                        int i = mi * 2 + half, r = rows[i];
                        *(float2*)(idbf + r * 64 + (cc - H)) =
                            make_float2(acc[mi][ni][half*2], acc[mi][ni][half*2+1]);
                    }
                }
            }
    }

    // --- stage B2: [64][128] hi & lo -> pitch 272 ---
    #pragma unroll
    for (int it = 0; it < 4; ++it) {
        int s = tid + it * THREADS;
        int buf = (s >= 1024);
        int t2 = s - buf * 1024;
        int n = t2 >> 4, j = t2 & 15;
        const char* srcp = (buf ? (const char*)g_W2T_lo : (const char*)g_W2T_hi)
                           + n * 256 + j * 16;
        *(uint4*)(smem + (buf ? OFF_B2LO : OFF_B2HI) + n * 272 + j * 16) =
            *(const uint4*)srcp;
    }
    __syncthreads();

    // ================= stage 2: [128,128] x [128,64] =================
    float ac2[2][2][4];
    #pragma unroll
    for (int mi = 0; mi < 2; ++mi)
        #pragma unroll
        for (int ni = 0; ni < 2; ++ni)
            #pragma unroll
            for (int j = 0; j < 4; ++j) ac2[mi][ni][j] = 0.0f;
    {
        const uint32_t a2Hi = sb + OFF_A2HI + (m0 + lrow) * 272 + kcol * 2;
        const uint32_t a2Lo = sb + OFF_A2LO + (m0 + lrow) * 272 + kcol * 2;
        const uint32_t b2Hi = sb + OFF_B2HI + (nw * 16 + brow) * 272 + bcol * 2;
        const uint32_t b2Lo = sb + OFF_B2LO + (nw * 16 + brow) * 272 + bcol * 2;
        #pragma unroll
        for (int ks = 0; ks < 8; ++ks) {
            const uint32_t ko = ks * 32;
            uint32_t ah[2][4], bh[4], al[2][4], bl[4];
            #pragma unroll
            for (int mi = 0; mi < 2; ++mi) ldsm_x4(a2Hi + mi * 4352 + ko, ah[mi]);
            ldsm_x4(b2Hi + ko, bh);
            #pragma unroll
            for (int mi = 0; mi < 2; ++mi)
                #pragma unroll
                for (int ni = 0; ni < 2; ++ni)
                    mma_bf16(ac2[mi][ni], ah[mi], &bh[ni * 2]);
            #pragma unroll
            for (int mi = 0; mi < 2; ++mi) ldsm_x4(a2Lo + mi * 4352 + ko, al[mi]);
            #pragma unroll
            for (int mi = 0; mi < 2; ++mi)
                #pragma unroll
                for (int ni = 0; ni < 2; ++ni)
                    mma_bf16(ac2[mi][ni], al[mi], &bh[ni * 2]);
            ldsm_x4(b2Lo + ko, bl);
            #pragma unroll
            for (int mi = 0; mi < 2; ++mi)
                #pragma unroll
                for (int ni = 0; ni < 2; ++ni)
                    mma_bf16(ac2[mi][ni], ah[mi], &bl[ni * 2]);
        }
    }
    __syncthreads();

    // ================= epilogue 2: bias, LN(64), +identity, GELU, dot W3 ============
    #pragma unroll
    for (int mi = 0; mi < 2; ++mi)
        #pragma unroll
        for (int ni = 0; ni < 2; ++ni) {
            int cc = nw * 16 + ni * 8 + qc;
            float2 bv = *(const float2*)(b2 + cc);
            ac2[mi][ni][0] += bv.x; ac2[mi][ni][1] += bv.y;
            ac2[mi][ni][2] += bv.x; ac2[mi][ni][3] += bv.y;
        }
    {
        float s[4] = {0,0,0,0}, q[4] = {0,0,0,0};
        #pragma unroll
        for (int mi = 0; mi < 2; ++mi)
            #pragma unroll
            for (int ni = 0; ni < 2; ++ni) {
                s[mi*2+0] += ac2[mi][ni][0] + ac2[mi][ni][1];
                q[mi*2+0] += ac2[mi][ni][0]*ac2[mi][ni][0] + ac2[mi][ni][1]*ac2[mi][ni][1];
                s[mi*2+1] += ac2[mi][ni][2] + ac2[mi][ni][3];
                q[mi*2+1] += ac2[mi][ni][2]*ac2[mi][ni][2] + ac2[mi][ni][3]*ac2[mi][ni][3];
            }
        #pragma unroll
        for (int i = 0; i < 4; ++i) {
            s[i] += __shfl_xor_sync(0xffffffffu, s[i], 1);
            s[i] += __shfl_xor_sync(0xffffffffu, s[i], 2);
            q[i] += __shfl_xor_sync(0xffffffffu, q[i], 1);
            q[i] += __shfl_xor_sync(0xffffffffu, q[i], 2);
        }
        if ((lane & 3) == 0) {
            #pragma unroll
            for (int i = 0; i < 4; ++i) {
                int r = m0 + qr + ((i & 1) ? 8 : 0) + ((i >> 1) ? 16 : 0);
                psum[r * 4 + nw] = s[i];
                psq [r * 4 + nw] = q[i];
            }
        }
    }
    __syncthreads();
    if (tid < MTILE) {
        float S = psum[tid*4] + psum[tid*4+1] + psum[tid*4+2] + psum[tid*4+3];
        float Q = psq [tid*4] + psq [tid*4+1] + psq [tid*4+2] + psq [tid*4+3];
        float mu = S * (1.0f / H2);
        mu_s[tid] = mu;
        rs_s[tid] = rsqrtf(Q * (1.0f / H2) - mu * mu + 1e-5f);
    }
    __syncthreads();
    {
        int rows[4];
        float muv[4], rsv[4], dotp[4] = {0,0,0,0};
        #pragma unroll
        for (int i = 0; i < 4; ++i) {
            rows[i] = m0 + qr + ((i & 1) ? 8 : 0) + ((i >> 1) ? 16 : 0);
            muv[i] = mu_s[rows[i]];
            rsv[i] = rs_s[rows[i]];
        }
        #pragma unroll
        for (int mi = 0; mi < 2; ++mi)
            #pragma unroll
            for (int ni = 0; ni < 2; ++ni) {
                int cc = nw * 16 + ni * 8 + qc;
                float2 gv = *(const float2*)(g2 + cc);
                float2 bev = *(const float2*)(be2 + cc);
                float2 wv = *(const float2*)(W3 + cc);
                #pragma unroll
                for (int half = 0; half < 2; ++half) {
                    int i = mi * 2 + half, r = rows[i];
                    float2 idv = *(const float2*)(idbf + r * 64 + cc);
                    float y0 = (ac2[mi][ni][half*2]   - muv[i]) * rsv[i] * gv.x + bev.x;
                    float y1 = (ac2[mi][ni][half*2+1] - muv[i]) * rsv[i] * gv.y + bev.y;
                    float h0 = gelu_exact(y0 + idv.x);
                    float h1 = gelu_exact(y1 + idv.y);
                    dotp[i] += h0 * wv.x + h1 * wv.y;
                }
            }
        #pragma unroll
        for (int i = 0; i < 4; ++i) {
            dotp[i] += __shfl_xor_sync(0xffffffffu, dotp[i], 1);
            dotp[i] += __shfl_xor_sync(0xffffffffu, dotp[i], 2);
        }
        __syncthreads();
        if ((lane & 3) == 0) {
            #pragma unroll
            for (int i = 0; i < 4; ++i)
                psum[rows[i] * 4 + nw] = dotp[i];
        }
    }
    __syncthreads();
    if (tid < MTILE && (e0 + tid) < E) {
        out[e0 + tid] = psum[tid*4] + psum[tid*4+1] + psum[tid*4+2] + psum[tid*4+3]
                        + b3[0];
    }
}

extern "C" void kernel_launch(void* const* d_in, const int* in_sizes, int n_in,
                              void* d_out, int out_size) {
    const float* drug = (const float*)d_in[0];
    const float* dis  = (const float*)d_in[1];
    const int*   src  = (const int*)  d_in[2];
    const int*   dst  = (const int*)  d_in[3];
    const float* W1   = (const float*)d_in[4];
    const float* b1   = (const float*)d_in[5];
    const float* g1   = (const float*)d_in[6];
    const float* be1  = (const float*)d_in[7];
    const float* W2   = (const float*)d_in[8];
    const float* b2   = (const float*)d_in[9];
    const float* g2   = (const float*)d_in[10];
    const float* be2  = (const float*)d_in[11];
    const float* W3   = (const float*)d_in[12];
    const float* b3   = (const float*)d_in[13];
    const float* Ws   = (const float*)d_in[14];
    const float* bs   = (const float*)d_in[15];
    const int E = in_sizes[2];

    prep_weights<<<(NC1 * KDIM + H2 * H + 255) / 256, 256>>>(W1, Ws, W2);

    cudaFuncSetAttribute(mlp_hmma_kernel,
                         cudaFuncAttributeMaxDynamicSharedMemorySize, SMEM_BYTES);
    const int grid = (E + MTILE - 1) / MTILE;
    mlp_hmma_kernel<<<grid, THREADS, SMEM_BYTES>>>(
        drug, dis, src, dst, b1, g1, be1, b2, g2, be2, W3, b3, bs,
        (float*)d_out, E);
}

// round 6
// speedup vs baseline: 3.1921x; 1.3303x over previous
#include <cuda_runtime.h>
#include <cuda_fp16.h>
#include <math.h>
#include <stdint.h>

// ---------------- problem dims ----------------
#define DFEAT 256
#define KDIM  512
#define H     128
#define H2    64
#define NC1   192          // fused stage-1 output cols (W1 | Ws)
#define MTILE 128          // edges per CTA
#define KC    64           // K-chunk
#define THREADS 512        // 16 warps: 4 m-warps x 4 n-warps

// ---------------- smem layout (bytes) ----------------
#define OFF_PS   0          // [128][4] float row partial sums
#define OFF_PQ   2048
#define OFF_MU   4096
#define OFF_RS   4608
#define OFF_RIDX 5120       // int[256]
// double-buffered stage-1 chunk sets (row pitch 144B = 64 fp16 + 16B pad)
#define CHUNK0   6144
#define A1HI_R   0          // 128*144 = 18432
#define A1LO_R   18432
#define B1_R     36864      // 192*144 = 27648
#define CHUNKSZ  64512
// phase 2 (aliases chunk buffers; pitch 272B = 128 fp16 + 16B pad)
#define OFF_A2HI 6144       // 128*272 = 34816
#define OFF_A2LO 40960
#define OFF_B2HI 75776      // 64*272 = 17408
#define OFF_B2LO 93184
#define OFF_ID   110592     // [128][64] float identity (ends 143360)
#define SMEM_BYTES 143360

// ---------------- prepped weights ----------------
__device__ __align__(16) __half g_WcatT[NC1 * KDIM];   // [n][k] fp16 (single)
__device__ __align__(16) __half g_W2T_hi[H2 * H];      // [n][k]
__device__ __align__(16) __half g_W2T_lo[H2 * H];

// ---------------- helpers ----------------
__device__ __forceinline__ uint32_t smem_u32(const void* p) {
    uint32_t a;
    asm("{ .reg .u64 t; cvta.to.shared.u64 t, %1; cvt.u32.u64 %0, t; }" : "=r"(a) : "l"(p));
    return a;
}
__device__ __forceinline__ void ldsm_x4(uint32_t addr, uint32_t* r) {
    asm volatile("ldmatrix.sync.aligned.m8n8.x4.shared.b16 {%0,%1,%2,%3}, [%4];"
        : "=r"(r[0]), "=r"(r[1]), "=r"(r[2]), "=r"(r[3]) : "r"(addr));
}
__device__ __forceinline__ void mma_f16(float* d, const uint32_t* a, const uint32_t* b) {
    asm volatile(
        "mma.sync.aligned.m16n8k16.row.col.f32.f16.f16.f32 "
        "{%0,%1,%2,%3}, {%4,%5,%6,%7}, {%8,%9}, {%0,%1,%2,%3};"
        : "+f"(d[0]), "+f"(d[1]), "+f"(d[2]), "+f"(d[3])
        : "r"(a[0]), "r"(a[1]), "r"(a[2]), "r"(a[3]), "r"(b[0]), "r"(b[1]));
}
__device__ __forceinline__ uint32_t pack_h(__half a, __half b) {
    return (uint32_t)__half_as_ushort(a) | ((uint32_t)__half_as_ushort(b) << 16);
}
__device__ __forceinline__ void split2h(float f, __half& h, __half& l) {
    h = __float2half_rn(f);
    l = __float2half_rn(f - __half2float(h));
}
__device__ __forceinline__ float gelu_exact(float x) {
    return 0.5f * x * (1.0f + erff(x * 0.70710678118654752440f));
}

// ---------------- prep kernel: convert/split + transpose weights ----------------
__global__ void prep_weights(const float* __restrict__ W1, const float* __restrict__ Ws,
                             const float* __restrict__ W2) {
    int i = blockIdx.x * 256 + threadIdx.x;
    if (i < NC1 * KDIM) {
        int n = i / KDIM, k = i % KDIM;
        float w = (n < H) ? W1[k * H + n] : Ws[k * H2 + (n - H)];
        g_WcatT[i] = __float2half_rn(w);
    } else {
        int j = i - NC1 * KDIM;
        if (j < H2 * H) {
            int n = j / H, k = j % H;
            float w = W2[k * H2 + n];
            __half h, l; split2h(w, h, l);
            g_W2T_hi[j] = h; g_W2T_lo[j] = l;
        }
    }
}

// ---------------- main kernel ----------------
__global__ void __launch_bounds__(THREADS, 1)
mlp_hmma_kernel(const float* __restrict__ drug, const float* __restrict__ dis,
                const int* __restrict__ src, const int* __restrict__ dst,
                const float* __restrict__ b1, const float* __restrict__ g1,
                const float* __restrict__ be1,
                const float* __restrict__ b2, const float* __restrict__ g2,
                const float* __restrict__ be2,
                const float* __restrict__ W3, const float* __restrict__ b3,
                const float* __restrict__ bs,
                float* __restrict__ out, int E)
{
    extern __shared__ char smem[];
    const uint32_t sb = smem_u32(smem);
    const int tid = threadIdx.x, wid = tid >> 5, lane = tid & 31;
    const int e0 = blockIdx.x * MTILE;

    float* psum = (float*)(smem + OFF_PS);
    float* psq  = (float*)(smem + OFF_PQ);
    float* mu_s = (float*)(smem + OFF_MU);
    float* rs_s = (float*)(smem + OFF_RS);
    int*   ridx = (int*)(smem + OFF_RIDX);
    float* idbf = (float*)(smem + OFF_ID);

    if (tid < MTILE) {
        int e = e0 + tid;
        ridx[tid]         = (e < E) ? src[e] : 0;
        ridx[MTILE + tid] = (e < E) ? dst[e] : 0;
    }
    __syncthreads();

    // warp tiling
    const int mw = wid >> 2, nw = wid & 3;
    const int m0 = mw * 32;
    const int n0 = nw * 48;
    const int lrow = lane & 15;
    const int kcol = (lane >> 4) * 8;
    const int brow = (lane & 7) + ((lane >> 4) * 8);
    const int bcol = ((lane >> 3) & 1) * 8;
    const int qr = lane >> 2;
    const int qc = (lane & 3) * 2;

    const uint32_t aoffA = (m0 + lrow) * 144 + kcol * 2;
    const uint32_t boffB = (n0 + brow) * 144 + bcol * 2;

    // staging coords
    const int grow = tid >> 2, gq = tid & 3;   // A gather: 128 rows x 4 thr

    float acc[2][6][4];
    #pragma unroll
    for (int mi = 0; mi < 2; ++mi)
        #pragma unroll
        for (int ni = 0; ni < 6; ++ni)
            #pragma unroll
            for (int j = 0; j < 4; ++j) acc[mi][ni][j] = 0.0f;

    float4 aReg[4];
    uint4  bReg[3];

    // ---- prefetch helpers ----
    auto load_chunk = [&](int cc) {
        const float* tab = (cc < 4) ? drug : dis;
        const long idx = (long)ridx[((cc < 4) ? 0 : MTILE) + grow];
        const float* sp = tab + idx * DFEAT + (cc & 3) * KC + gq * 16;
        #pragma unroll
        for (int j = 0; j < 4; ++j) aReg[j] = *(const float4*)(sp + 4 * j);
        // B tile: 192 rows x 8 uint4 slots = 1536 slots = exactly 3 iterations
        #pragma unroll
        for (int it = 0; it < 3; ++it) {
            int s = tid + it * THREADS;        // 0..1535
            int n = s >> 3, j = s & 7;
            bReg[it] = *(const uint4*)((const char*)g_WcatT + n * 1024 + cc * 128 + j * 16);
        }
    };
    auto store_chunk = [&](int bsel) {
        char* base = smem + CHUNK0 + bsel * CHUNKSZ;
        char* dh = base + A1HI_R + grow * 144 + gq * 32;
        char* dl = base + A1LO_R + grow * 144 + gq * 32;
        #pragma unroll
        for (int j = 0; j < 4; ++j) {
            __half h0,h1,h2,h3,l0,l1,l2,l3;
            split2h(aReg[j].x, h0, l0); split2h(aReg[j].y, h1, l1);
            split2h(aReg[j].z, h2, l2); split2h(aReg[j].w, h3, l3);
            *(uint2*)(dh + j * 8) = make_uint2(pack_h(h0,h1), pack_h(h2,h3));
            *(uint2*)(dl + j * 8) = make_uint2(pack_h(l0,l1), pack_h(l2,l3));
        }
        #pragma unroll
        for (int it = 0; it < 3; ++it) {
            int s = tid + it * THREADS;        // 0..1535
            int n = s >> 3, j = s & 7;
            *(uint4*)(base + B1_R + n * 144 + j * 16) = bReg[it];
        }
    };

    // ================= stage 1: pipelined, double-buffered, 2 passes =================
    load_chunk(0);
    store_chunk(0);
    load_chunk(1);
    __syncthreads();

    for (int c = 0; c < 8; ++c) {
        if (c < 7) store_chunk((c + 1) & 1);
        if (c < 6) load_chunk(c + 2);

        const uint32_t cb = sb + CHUNK0 + ((c & 1) ? CHUNKSZ : 0);
        const uint32_t aHi = cb + A1HI_R + aoffA;
        const uint32_t aLo = cb + A1LO_R + aoffA;
        const uint32_t bB  = cb + B1_R   + boffB;

        #pragma unroll
        for (int ks = 0; ks < 4; ++ks) {
            const uint32_t ko = ks * 32;
            uint32_t ah[2][4], al[2][4], bf[3][4];
            #pragma unroll
            for (int mi = 0; mi < 2; ++mi) ldsm_x4(aHi + mi * 2304 + ko, ah[mi]);
            #pragma unroll
            for (int p = 0; p < 3; ++p)    ldsm_x4(bB + p * 2304 + ko, bf[p]);
            #pragma unroll
            for (int mi = 0; mi < 2; ++mi)
                #pragma unroll
                for (int ni = 0; ni < 6; ++ni)
                    mma_f16(acc[mi][ni], ah[mi], &bf[ni >> 1][(ni & 1) * 2]);
            #pragma unroll
            for (int mi = 0; mi < 2; ++mi) ldsm_x4(aLo + mi * 2304 + ko, al[mi]);
            #pragma unroll
            for (int mi = 0; mi < 2; ++mi)
                #pragma unroll
                for (int ni = 0; ni < 6; ++ni)
                    mma_f16(acc[mi][ni], al[mi], &bf[ni >> 1][(ni & 1) * 2]);
        }
        __syncthreads();
    }

    // ================= epilogue 1: bias, LN(128), GELU, split -> A2; identity -> idbf ====
    #pragma unroll
    for (int mi = 0; mi < 2; ++mi)
        #pragma unroll
        for (int ni = 0; ni < 6; ++ni) {
            int cc = n0 + ni * 8 + qc;
            float2 bv = (cc < H) ? *(const float2*)(b1 + cc)
                                 : *(const float2*)(bs + cc - H);
            acc[mi][ni][0] += bv.x; acc[mi][ni][1] += bv.y;
            acc[mi][ni][2] += bv.x; acc[mi][ni][3] += bv.y;
        }
    {
        const int nLim = (nw < 2) ? 6 : ((nw == 2) ? 4 : 0);
        float s[4] = {0,0,0,0}, q[4] = {0,0,0,0};
        for (int mi = 0; mi < 2; ++mi)
            for (int ni = 0; ni < nLim; ++ni) {
                s[mi*2+0] += acc[mi][ni][0] + acc[mi][ni][1];
                q[mi*2+0] += acc[mi][ni][0]*acc[mi][ni][0] + acc[mi][ni][1]*acc[mi][ni][1];
                s[mi*2+1] += acc[mi][ni][2] + acc[mi][ni][3];
                q[mi*2+1] += acc[mi][ni][2]*acc[mi][ni][2] + acc[mi][ni][3]*acc[mi][ni][3];
            }
        #pragma unroll
        for (int i = 0; i < 4; ++i) {
            s[i] += __shfl_xor_sync(0xffffffffu, s[i], 1);
            s[i] += __shfl_xor_sync(0xffffffffu, s[i], 2);
            q[i] += __shfl_xor_sync(0xffffffffu, q[i], 1);
            q[i] += __shfl_xor_sync(0xffffffffu, q[i], 2);
        }
        if ((lane & 3) == 0 && nw < 3) {
            #pragma unroll
            for (int i = 0; i < 4; ++i) {
                int r = m0 + qr + ((i & 1) ? 8 : 0) + ((i >> 1) ? 16 : 0);
                psum[r * 4 + nw] = s[i];
                psq [r * 4 + nw] = q[i];
            }
        }
    }
    __syncthreads();
    if (tid < MTILE) {
        float S = psum[tid*4] + psum[tid*4+1] + psum[tid*4+2];
        float Q = psq [tid*4] + psq [tid*4+1] + psq [tid*4+2];
        float mu = S * (1.0f / H);
        mu_s[tid] = mu;
        rs_s[tid] = rsqrtf(Q * (1.0f / H) - mu * mu + 1e-5f);
    }
    __syncthreads();
    {
        int rows[4];
        float muv[4], rsv[4];
        #pragma unroll
        for (int i = 0; i < 4; ++i) {
            rows[i] = m0 + qr + ((i & 1) ? 8 : 0) + ((i >> 1) ? 16 : 0);
            muv[i] = mu_s[rows[i]];
            rsv[i] = rs_s[rows[i]];
        }
        #pragma unroll
        for (int mi = 0; mi < 2; ++mi)
            #pragma unroll
            for (int ni = 0; ni < 6; ++ni) {
                int cc = n0 + ni * 8 + qc;
                if (cc < H) {
                    float2 gv = *(const float2*)(g1 + cc);
                    float2 bev = *(const float2*)(be1 + cc);
                    #pragma unroll
                    for (int half = 0; half < 2; ++half) {
                        int i = mi * 2 + half, r = rows[i];
                        float y0 = (acc[mi][ni][half*2]   - muv[i]) * rsv[i] * gv.x + bev.x;
                        float y1 = (acc[mi][ni][half*2+1] - muv[i]) * rsv[i] * gv.y + bev.y;
                        float h0 = gelu_exact(y0), h1 = gelu_exact(y1);
                        __half hh0,ll0,hh1,ll1;
                        split2h(h0, hh0, ll0); split2h(h1, hh1, ll1);
                        *(uint32_t*)(smem + OFF_A2HI + r * 272 + cc * 2) = pack_h(hh0, hh1);
                        *(uint32_t*)(smem + OFF_A2LO + r * 272 + cc * 2) = pack_h(ll0, ll1);
                    }
                } else {
                    #pragma unroll
                    for (int half = 0; half < 2; ++half) {
                        int i = mi * 2 + half, r = rows[i];
                        *(float2*)(idbf + r * 64 + (cc - H)) =
                            make_float2(acc[mi][ni][half*2], acc[mi][ni][half*2+1]);
                    }
                }
            }
    }

    // --- stage B2: [64][128] hi & lo -> pitch 272 ---
    #pragma unroll
    for (int it = 0; it < 4; ++it) {
        int s = tid + it * THREADS;        // 0..2047 (2 x 1024 slots)
        int buf = (s >= 1024);
        int t2 = s - buf * 1024;
        int n = t2 >> 4, j = t2 & 15;
        const char* srcp = (buf ? (const char*)g_W2T_lo : (const char*)g_W2T_hi)
                           + n * 256 + j * 16;
        *(uint4*)(smem + (buf ? OFF_B2LO : OFF_B2HI) + n * 272 + j * 16) =
            *(const uint4*)srcp;
    }
    __syncthreads();

    // ================= stage 2: [128,128] x [128,64], 3 passes =================
    float ac2[2][2][4];
    #pragma unroll
    for (int mi = 0; mi < 2; ++mi)
        #pragma unroll
        for (int ni = 0; ni < 2; ++ni)
            #pragma unroll
            for (int j = 0; j < 4; ++j) ac2[mi][ni][j] = 0.0f;
    {
        const uint32_t a2Hi = sb + OFF_A2HI + (m0 + lrow) * 272 + kcol * 2;
        const uint32_t a2Lo = sb + OFF_A2LO + (m0 + lrow) * 272 + kcol * 2;
        const uint32_t b2Hi = sb + OFF_B2HI + (nw * 16 + brow) * 272 + bcol * 2;
        const uint32_t b2Lo = sb + OFF_B2LO + (nw * 16 + brow) * 272 + bcol * 2;
        #pragma unroll
        for (int ks = 0; ks < 8; ++ks) {
            const uint32_t ko = ks * 32;
            uint32_t ah[2][4], bh[4], al[2][4], bl[4];
            #pragma unroll
            for (int mi = 0; mi < 2; ++mi) ldsm_x4(a2Hi + mi * 4352 + ko, ah[mi]);
            ldsm_x4(b2Hi + ko, bh);
            #pragma unroll
            for (int mi = 0; mi < 2; ++mi)
                #pragma unroll
                for (int ni = 0; ni < 2; ++ni)
                    mma_f16(ac2[mi][ni], ah[mi], &bh[ni * 2]);
            #pragma unroll
            for (int mi = 0; mi < 2; ++mi) ldsm_x4(a2Lo + mi * 4352 + ko, al[mi]);
            #pragma unroll
            for (int mi = 0; mi < 2; ++mi)
                #pragma unroll
                for (int ni = 0; ni < 2; ++ni)
                    mma_f16(ac2[mi][ni], al[mi], &bh[ni * 2]);
            ldsm_x4(b2Lo + ko, bl);
            #pragma unroll
            for (int mi = 0; mi < 2; ++mi)
                #pragma unroll
                for (int ni = 0; ni < 2; ++ni)
                    mma_f16(ac2[mi][ni], ah[mi], &bl[ni * 2]);
        }
    }
    __syncthreads();

    // ================= epilogue 2: bias, LN(64), +identity, GELU, dot W3 ============
    #pragma unroll
    for (int mi = 0; mi < 2; ++mi)
        #pragma unroll
        for (int ni = 0; ni < 2; ++ni) {
            int cc = nw * 16 + ni * 8 + qc;
            float2 bv = *(const float2*)(b2 + cc);
            ac2[mi][ni][0] += bv.x; ac2[mi][ni][1] += bv.y;
            ac2[mi][ni][2] += bv.x; ac2[mi][ni][3] += bv.y;
        }
    {
        float s[4] = {0,0,0,0}, q[4] = {0,0,0,0};
        #pragma unroll
        for (int mi = 0; mi < 2; ++mi)
            #pragma unroll
            for (int ni = 0; ni < 2; ++ni) {
                s[mi*2+0] += ac2[mi][ni][0] + ac2[mi][ni][1];
                q[mi*2+0] += ac2[mi][ni][0]*ac2[mi][ni][0] + ac2[mi][ni][1]*ac2[mi][ni][1];
                s[mi*2+1] += ac2[mi][ni][2] + ac2[mi][ni][3];
                q[mi*2+1] += ac2[mi][ni][2]*ac2[mi][ni][2] + ac2[mi][ni][3]*ac2[mi][ni][3];
            }
        #pragma unroll
        for (int i = 0; i < 4; ++i) {
            s[i] += __shfl_xor_sync(0xffffffffu, s[i], 1);
            s[i] += __shfl_xor_sync(0xffffffffu, s[i], 2);
            q[i] += __shfl_xor_sync(0xffffffffu, q[i], 1);
            q[i] += __shfl_xor_sync(0xffffffffu, q[i], 2);
        }
        if ((lane & 3) == 0) {
            #pragma unroll
            for (int i = 0; i < 4; ++i) {
                int r = m0 + qr + ((i & 1) ? 8 : 0) + ((i >> 1) ? 16 : 0);
                psum[r * 4 + nw] = s[i];
                psq [r * 4 + nw] = q[i];
            }
        }
    }
    __syncthreads();
    if (tid < MTILE) {
        float S = psum[tid*4] + psum[tid*4+1] + psum[tid*4+2] + psum[tid*4+3];
        float Q = psq [tid*4] + psq [tid*4+1] + psq [tid*4+2] + psq [tid*4+3];
        float mu = S * (1.0f / H2);
        mu_s[tid] = mu;
        rs_s[tid] = rsqrtf(Q * (1.0f / H2) - mu * mu + 1e-5f);
    }
    __syncthreads();
    {
        int rows[4];
        float muv[4], rsv[4], dotp[4] = {0,0,0,0};
        #pragma unroll
        for (int i = 0; i < 4; ++i) {
            rows[i] = m0 + qr + ((i & 1) ? 8 : 0) + ((i >> 1) ? 16 : 0);
            muv[i] = mu_s[rows[i]];
            rsv[i] = rs_s[rows[i]];
        }
        #pragma unroll
        for (int mi = 0; mi < 2; ++mi)
            #pragma unroll
            for (int ni = 0; ni < 2; ++ni) {
                int cc = nw * 16 + ni * 8 + qc;
                float2 gv = *(const float2*)(g2 + cc);
                float2 bev = *(const float2*)(be2 + cc);
                float2 wv = *(const float2*)(W3 + cc);
                #pragma unroll
                for (int half = 0; half < 2; ++half) {
                    int i = mi * 2 + half, r = rows[i];
                    float2 idv = *(const float2*)(idbf + r * 64 + cc);
                    float y0 = (ac2[mi][ni][half*2]   - muv[i]) * rsv[i] * gv.x + bev.x;
                    float y1 = (ac2[mi][ni][half*2+1] - muv[i]) * rsv[i] * gv.y + bev.y;
                    float h0 = gelu_exact(y0 + idv.x);
                    float h1 = gelu_exact(y1 + idv.y);
                    dotp[i] += h0 * wv.x + h1 * wv.y;
                }
            }
        #pragma unroll
        for (int i = 0; i < 4; ++i) {
            dotp[i] += __shfl_xor_sync(0xffffffffu, dotp[i], 1);
            dotp[i] += __shfl_xor_sync(0xffffffffu, dotp[i], 2);
        }
        __syncthreads();
        if ((lane & 3) == 0) {
            #pragma unroll
            for (int i = 0; i < 4; ++i)
                psum[rows[i] * 4 + nw] = dotp[i];
        }
    }
    __syncthreads();
    if (tid < MTILE && (e0 + tid) < E) {
        out[e0 + tid] = psum[tid*4] + psum[tid*4+1] + psum[tid*4+2] + psum[tid*4+3]
                        + b3[0];
    }
}

extern "C" void kernel_launch(void* const* d_in, const int* in_sizes, int n_in,
                              void* d_out, int out_size) {
    const float* drug = (const float*)d_in[0];
    const float* dis  = (const float*)d_in[1];
    const int*   src  = (const int*)  d_in[2];
    const int*   dst  = (const int*)  d_in[3];
    const float* W1   = (const float*)d_in[4];
    const float* b1   = (const float*)d_in[5];
    const float* g1   = (const float*)d_in[6];
    const float* be1  = (const float*)d_in[7];
    const float* W2   = (const float*)d_in[8];
    const float* b2   = (const float*)d_in[9];
    const float* g2   = (const float*)d_in[10];
    const float* be2  = (const float*)d_in[11];
    const float* W3   = (const float*)d_in[12];
    const float* b3   = (const float*)d_in[13];
    const float* Ws   = (const float*)d_in[14];
    const float* bs   = (const float*)d_in[15];
    const int E = in_sizes[2];

    prep_weights<<<(NC1 * KDIM + H2 * H + 255) / 256, 256>>>(W1, Ws, W2);

    cudaFuncSetAttribute(mlp_hmma_kernel,
                         cudaFuncAttributeMaxDynamicSharedMemorySize, SMEM_BYTES);
    const int grid = (E + MTILE - 1) / MTILE;
    mlp_hmma_kernel<<<grid, THREADS, SMEM_BYTES>>>(
        drug, dis, src, dst, b1, g1, be1, b2, g2, be2, W3, b3, bs,
        (float*)d_out, E);
}

// round 7
// speedup vs baseline: 3.1930x; 1.0003x over previous
#include <cuda_runtime.h>
#include <cuda_fp16.h>
#include <math.h>
#include <stdint.h>

// ---------------- problem dims ----------------
#define DFEAT 256
#define KDIM  512
#define H     128
#define H2    64
#define NC1   192          // fused stage-1 output cols (W1 | Ws)
#define MTILE 128          // edges per CTA
#define KC    64           // K-chunk
#define THREADS 512        // 16 warps: 4 m-warps x 4 n-warps

// ---------------- smem layout (bytes) ----------------
#define OFF_PS   0          // [128][4] float row partial sums
#define OFF_PQ   2048
#define OFF_MU   4096
#define OFF_RS   4608
#define OFF_RIDX 5120       // int[256]
// double-buffered stage-1 chunk sets (row pitch 144B = 64 fp16 + 16B pad)
#define CHUNK0   6144
#define A1HI_R   0          // 128*144 = 18432
#define A1LO_R   18432
#define B1_R     36864      // 192*144 = 27648
#define CHUNKSZ  64512
// phase 2 (aliases chunk buffers; pitch 272B = 128 fp16 + 16B pad)
#define OFF_A2HI 6144       // 128*272 = 34816
#define OFF_A2LO 40960
#define OFF_B2HI 75776      // 64*272 = 17408
#define OFF_B2LO 93184
#define OFF_ID   110592     // [128][64] float identity (ends 143360)
#define SMEM_BYTES 143360

// ---------------- prepped weights ----------------
__device__ __align__(16) __half g_WcatT[NC1 * KDIM];   // [n][k] fp16 (single)
__device__ __align__(16) __half g_W2T_hi[H2 * H];      // [n][k]
__device__ __align__(16) __half g_W2T_lo[H2 * H];

// ---------------- helpers ----------------
__device__ __forceinline__ uint32_t smem_u32(const void* p) {
    uint32_t a;
    asm("{ .reg .u64 t; cvta.to.shared.u64 t, %1; cvt.u32.u64 %0, t; }" : "=r"(a) : "l"(p));
    return a;
}
__device__ __forceinline__ void ldsm_x4(uint32_t addr, uint32_t* r) {
    asm volatile("ldmatrix.sync.aligned.m8n8.x4.shared.b16 {%0,%1,%2,%3}, [%4];"
        : "=r"(r[0]), "=r"(r[1]), "=r"(r[2]), "=r"(r[3]) : "r"(addr));
}
__device__ __forceinline__ void mma_f16(float* d, const uint32_t* a, const uint32_t* b) {
    asm volatile(
        "mma.sync.aligned.m16n8k16.row.col.f32.f16.f16.f32 "
        "{%0,%1,%2,%3}, {%4,%5,%6,%7}, {%8,%9}, {%0,%1,%2,%3};"
        : "+f"(d[0]), "+f"(d[1]), "+f"(d[2]), "+f"(d[3])
        : "r"(a[0]), "r"(a[1]), "r"(a[2]), "r"(a[3]), "r"(b[0]), "r"(b[1]));
}
__device__ __forceinline__ uint32_t pack_h(__half a, __half b) {
    return (uint32_t)__half_as_ushort(a) | ((uint32_t)__half_as_ushort(b) << 16);
}
__device__ __forceinline__ void split2h(float f, __half& h, __half& l) {
    h = __float2half_rn(f);
    l = __float2half_rn(f - __half2float(h));
}
__device__ __forceinline__ float gelu_exact(float x) {
    return 0.5f * x * (1.0f + erff(x * 0.70710678118654752440f));
}

// ---------------- prep kernel: convert/split + transpose weights ----------------
__global__ void prep_weights(const float* __restrict__ W1, const float* __restrict__ Ws,
                             const float* __restrict__ W2) {
    int i = blockIdx.x * 256 + threadIdx.x;
    if (i < NC1 * KDIM) {
        int n = i / KDIM, k = i % KDIM;
        float w = (n < H) ? W1[k * H + n] : Ws[k * H2 + (n - H)];
        g_WcatT[i] = __float2half_rn(w);
    } else {
        int j = i - NC1 * KDIM;
        if (j < H2 * H) {
            int n = j / H, k = j % H;
            float w = W2[k * H2 + n];
            __half h, l; split2h(w, h, l);
            g_W2T_hi[j] = h; g_W2T_lo[j] = l;
        }
    }
}

// ---------------- main kernel ----------------
__global__ void __launch_bounds__(THREADS, 1)
mlp_hmma_kernel(const float* __restrict__ drug, const float* __restrict__ dis,
                const int* __restrict__ src, const int* __restrict__ dst,
                const float* __restrict__ b1, const float* __restrict__ g1,
                const float* __restrict__ be1,
                const float* __restrict__ b2, const float* __restrict__ g2,
                const float* __restrict__ be2,
                const float* __restrict__ W3, const float* __restrict__ b3,
                const float* __restrict__ bs,
                float* __restrict__ out, int E)
{
    extern __shared__ char smem[];
    const uint32_t sb = smem_u32(smem);
    const int tid = threadIdx.x, wid = tid >> 5, lane = tid & 31;
    const int e0 = blockIdx.x * MTILE;

    float* psum = (float*)(smem + OFF_PS);
    float* psq  = (float*)(smem + OFF_PQ);
    float* mu_s = (float*)(smem + OFF_MU);
    float* rs_s = (float*)(smem + OFF_RS);
    int*   ridx = (int*)(smem + OFF_RIDX);
    float* idbf = (float*)(smem + OFF_ID);

    if (tid < MTILE) {
        int e = e0 + tid;
        ridx[tid]         = (e < E) ? src[e] : 0;
        ridx[MTILE + tid] = (e < E) ? dst[e] : 0;
    }
    __syncthreads();

    // warp tiling
    const int mw = wid >> 2, nw = wid & 3;
    const int m0 = mw * 32;
    const int n0 = nw * 48;
    const int lrow = lane & 15;
    const int kcol = (lane >> 4) * 8;
    const int brow = (lane & 7) + ((lane >> 4) * 8);
    const int bcol = ((lane >> 3) & 1) * 8;
    const int qr = lane >> 2;
    const int qc = (lane & 3) * 2;

    const uint32_t aoffA = (m0 + lrow) * 144 + kcol * 2;
    const uint32_t boffB = (n0 + brow) * 144 + bcol * 2;

    // staging coords
    const int grow = tid >> 2, gq = tid & 3;   // A gather: 128 rows x 4 thr

    float acc[2][6][4];
    #pragma unroll
    for (int mi = 0; mi < 2; ++mi)
        #pragma unroll
        for (int ni = 0; ni < 6; ++ni)
            #pragma unroll
            for (int j = 0; j < 4; ++j) acc[mi][ni][j] = 0.0f;

    float4 aReg[4];
    uint4  bReg[3];

    // ---- prefetch helpers ----
    auto load_chunk = [&](int cc) {
        const float* tab = (cc < 4) ? drug : dis;
        const long idx = (long)ridx[((cc < 4) ? 0 : MTILE) + grow];
        const float* sp = tab + idx * DFEAT + (cc & 3) * KC + gq * 16;
        #pragma unroll
        for (int j = 0; j < 4; ++j) aReg[j] = *(const float4*)(sp + 4 * j);
        // B tile: 192 rows x 8 uint4 slots = 1536 slots = exactly 3 iterations
        #pragma unroll
        for (int it = 0; it < 3; ++it) {
            int s = tid + it * THREADS;        // 0..1535
            int n = s >> 3, j = s & 7;
            bReg[it] = *(const uint4*)((const char*)g_WcatT + n * 1024 + cc * 128 + j * 16);
        }
    };
    auto store_chunk = [&](int bsel) {
        char* base = smem + CHUNK0 + bsel * CHUNKSZ;
        char* dh = base + A1HI_R + grow * 144 + gq * 32;
        char* dl = base + A1LO_R + grow * 144 + gq * 32;
        #pragma unroll
        for (int j = 0; j < 4; ++j) {
            __half h0,h1,h2,h3,l0,l1,l2,l3;
            split2h(aReg[j].x, h0, l0); split2h(aReg[j].y, h1, l1);
            split2h(aReg[j].z, h2, l2); split2h(aReg[j].w, h3, l3);
            *(uint2*)(dh + j * 8) = make_uint2(pack_h(h0,h1), pack_h(h2,h3));
            *(uint2*)(dl + j * 8) = make_uint2(pack_h(l0,l1), pack_h(l2,l3));
        }
        #pragma unroll
        for (int it = 0; it < 3; ++it) {
            int s = tid + it * THREADS;        // 0..1535
            int n = s >> 3, j = s & 7;
            *(uint4*)(base + B1_R + n * 144 + j * 16) = bReg[it];
        }
    };

    // ================= stage 1: pipelined, double-buffered, 2 passes =================
    load_chunk(0);
    store_chunk(0);
    load_chunk(1);
    __syncthreads();

    for (int c = 0; c < 8; ++c) {
        if (c < 7) store_chunk((c + 1) & 1);
        if (c < 6) load_chunk(c + 2);

        const uint32_t cb = sb + CHUNK0 + ((c & 1) ? CHUNKSZ : 0);
        const uint32_t aHi = cb + A1HI_R + aoffA;
        const uint32_t aLo = cb + A1LO_R + aoffA;
        const uint32_t bB  = cb + B1_R   + boffB;

        #pragma unroll
        for (int ks = 0; ks < 4; ++ks) {
            const uint32_t ko = ks * 32;
            uint32_t ah[2][4], al[2][4], bf[3][4];
            #pragma unroll
            for (int mi = 0; mi < 2; ++mi) ldsm_x4(aHi + mi * 2304 + ko, ah[mi]);
            #pragma unroll
            for (int p = 0; p < 3; ++p)    ldsm_x4(bB + p * 2304 + ko, bf[p]);
            #pragma unroll
            for (int mi = 0; mi < 2; ++mi)
                #pragma unroll
                for (int ni = 0; ni < 6; ++ni)
                    mma_f16(acc[mi][ni], ah[mi], &bf[ni >> 1][(ni & 1) * 2]);
            #pragma unroll
            for (int mi = 0; mi < 2; ++mi) ldsm_x4(aLo + mi * 2304 + ko, al[mi]);
            #pragma unroll
            for (int mi = 0; mi < 2; ++mi)
                #pragma unroll
                for (int ni = 0; ni < 6; ++ni)
                    mma_f16(acc[mi][ni], al[mi], &bf[ni >> 1][(ni & 1) * 2]);
        }
        __syncthreads();
    }

    // ================= epilogue 1: bias, LN(128), GELU, split -> A2; identity -> idbf ====
    #pragma unroll
    for (int mi = 0; mi < 2; ++mi)
        #pragma unroll
        for (int ni = 0; ni < 6; ++ni) {
            int cc = n0 + ni * 8 + qc;
            float2 bv = (cc < H) ? *(const float2*)(b1 + cc)
                                 : *(const float2*)(bs + cc - H);
            acc[mi][ni][0] += bv.x; acc[mi][ni][1] += bv.y;
            acc[mi][ni][2] += bv.x; acc[mi][ni][3] += bv.y;
        }
    {
        const int nLim = (nw < 2) ? 6 : ((nw == 2) ? 4 : 0);
        float s[4] = {0,0,0,0}, q[4] = {0,0,0,0};
        for (int mi = 0; mi < 2; ++mi)
            for (int ni = 0; ni < nLim; ++ni) {
                s[mi*2+0] += acc[mi][ni][0] + acc[mi][ni][1];
                q[mi*2+0] += acc[mi][ni][0]*acc[mi][ni][0] + acc[mi][ni][1]*acc[mi][ni][1];
                s[mi*2+1] += acc[mi][ni][2] + acc[mi][ni][3];
                q[mi*2+1] += acc[mi][ni][2]*acc[mi][ni][2] + acc[mi][ni][3]*acc[mi][ni][3];
            }
        #pragma unroll
        for (int i = 0; i < 4; ++i) {
            s[i] += __shfl_xor_sync(0xffffffffu, s[i], 1);
            s[i] += __shfl_xor_sync(0xffffffffu, s[i], 2);
            q[i] += __shfl_xor_sync(0xffffffffu, q[i], 1);
            q[i] += __shfl_xor_sync(0xffffffffu, q[i], 2);
        }
        if ((lane & 3) == 0 && nw < 3) {
            #pragma unroll
            for (int i = 0; i < 4; ++i) {
                int r = m0 + qr + ((i & 1) ? 8 : 0) + ((i >> 1) ? 16 : 0);
                psum[r * 4 + nw] = s[i];
                psq [r * 4 + nw] = q[i];
            }
        }
    }
    __syncthreads();
    if (tid < MTILE) {
        float S = psum[tid*4] + psum[tid*4+1] + psum[tid*4+2];
        float Q = psq [tid*4] + psq [tid*4+1] + psq [tid*4+2];
        float mu = S * (1.0f / H);
        mu_s[tid] = mu;
        rs_s[tid] = rsqrtf(Q * (1.0f / H) - mu * mu + 1e-5f);
    }
    __syncthreads();
    {
        int rows[4];
        float muv[4], rsv[4];
        #pragma unroll
        for (int i = 0; i < 4; ++i) {
            rows[i] = m0 + qr + ((i & 1) ? 8 : 0) + ((i >> 1) ? 16 : 0);
            muv[i] = mu_s[rows[i]];
            rsv[i] = rs_s[rows[i]];
        }
        #pragma unroll
        for (int mi = 0; mi < 2; ++mi)
            #pragma unroll
            for (int ni = 0; ni < 6; ++ni) {
                int cc = n0 + ni * 8 + qc;
                if (cc < H) {
                    float2 gv = *(const float2*)(g1 + cc);
                    float2 bev = *(const float2*)(be1 + cc);
                    #pragma unroll
                    for (int half = 0; half < 2; ++half) {
                        int i = mi * 2 + half, r = rows[i];
                        float y0 = (acc[mi][ni][half*2]   - muv[i]) * rsv[i] * gv.x + bev.x;
                        float y1 = (acc[mi][ni][half*2+1] - muv[i]) * rsv[i] * gv.y + bev.y;
                        float h0 = gelu_exact(y0), h1 = gelu_exact(y1);
                        __half hh0,ll0,hh1,ll1;
                        split2h(h0, hh0, ll0); split2h(h1, hh1, ll1);
                        *(uint32_t*)(smem + OFF_A2HI + r * 272 + cc * 2) = pack_h(hh0, hh1);
                        *(uint32_t*)(smem + OFF_A2LO + r * 272 + cc * 2) = pack_h(ll0, ll1);
                    }
                } else {
                    #pragma unroll
                    for (int half = 0; half < 2; ++half) {
                        int i = mi * 2 + half, r = rows[i];
                        *(float2*)(idbf + r * 64 + (cc - H)) =
                            make_float2(acc[mi][ni][half*2], acc[mi][ni][half*2+1]);
                    }
                }
            }
    }

    // --- stage B2: [64][128] hi & lo -> pitch 272 ---
    #pragma unroll
    for (int it = 0; it < 4; ++it) {
        int s = tid + it * THREADS;        // 0..2047 (2 x 1024 slots)
        int buf = (s >= 1024);
        int t2 = s - buf * 1024;
        int n = t2 >> 4, j = t2 & 15;
        const char* srcp = (buf ? (const char*)g_W2T_lo : (const char*)g_W2T_hi)
                           + n * 256 + j * 16;
        *(uint4*)(smem + (buf ? OFF_B2LO : OFF_B2HI) + n * 272 + j * 16) =
            *(const uint4*)srcp;
    }
    __syncthreads();

    // ================= stage 2: [128,128] x [128,64], 3 passes =================
    float ac2[2][2][4];
    #pragma unroll
    for (int mi = 0; mi < 2; ++mi)
        #pragma unroll
        for (int ni = 0; ni < 2; ++ni)
            #pragma unroll
            for (int j = 0; j < 4; ++j) ac2[mi][ni][j] = 0.0f;
    {
        const uint32_t a2Hi = sb + OFF_A2HI + (m0 + lrow) * 272 + kcol * 2;
        const uint32_t a2Lo = sb + OFF_A2LO + (m0 + lrow) * 272 + kcol * 2;
        const uint32_t b2Hi = sb + OFF_B2HI + (nw * 16 + brow) * 272 + bcol * 2;
        const uint32_t b2Lo = sb + OFF_B2LO + (nw * 16 + brow) * 272 + bcol * 2;
        #pragma unroll
        for (int ks = 0; ks < 8; ++ks) {
            const uint32_t ko = ks * 32;
            uint32_t ah[2][4], bh[4], al[2][4], bl[4];
            #pragma unroll
            for (int mi = 0; mi < 2; ++mi) ldsm_x4(a2Hi + mi * 4352 + ko, ah[mi]);
            ldsm_x4(b2Hi + ko, bh);
            #pragma unroll
            for (int mi = 0; mi < 2; ++mi)
                #pragma unroll
                for (int ni = 0; ni < 2; ++ni)
                    mma_f16(ac2[mi][ni], ah[mi], &bh[ni * 2]);
            #pragma unroll
            for (int mi = 0; mi < 2; ++mi) ldsm_x4(a2Lo + mi * 4352 + ko, al[mi]);
            #pragma unroll
            for (int mi = 0; mi < 2; ++mi)
                #pragma unroll
                for (int ni = 0; ni < 2; ++ni)
                    mma_f16(ac2[mi][ni], al[mi], &bh[ni * 2]);
            ldsm_x4(b2Lo + ko, bl);
            #pragma unroll
            for (int mi = 0; mi < 2; ++mi)
                #pragma unroll
                for (int ni = 0; ni < 2; ++ni)
                    mma_f16(ac2[mi][ni], ah[mi], &bl[ni * 2]);
        }
    }
    __syncthreads();

    // ================= epilogue 2: bias, LN(64), +identity, GELU, dot W3 ============
    #pragma unroll
    for (int mi = 0; mi < 2; ++mi)
        #pragma unroll
        for (int ni = 0; ni < 2; ++ni) {
            int cc = nw * 16 + ni * 8 + qc;
            float2 bv = *(const float2*)(b2 + cc);
            ac2[mi][ni][0] += bv.x; ac2[mi][ni][1] += bv.y;
            ac2[mi][ni][2] += bv.x; ac2[mi][ni][3] += bv.y;
        }
    {
        float s[4] = {0,0,0,0}, q[4] = {0,0,0,0};
        #pragma unroll
        for (int mi = 0; mi < 2; ++mi)
            #pragma unroll
            for (int ni = 0; ni < 2; ++ni) {
                s[mi*2+0] += ac2[mi][ni][0] + ac2[mi][ni][1];
                q[mi*2+0] += ac2[mi][ni][0]*ac2[mi][ni][0] + ac2[mi][ni][1]*ac2[mi][ni][1];
                s[mi*2+1] += ac2[mi][ni][2] + ac2[mi][ni][3];
                q[mi*2+1] += ac2[mi][ni][2]*ac2[mi][ni][2] + ac2[mi][ni][3]*ac2[mi][ni][3];
            }
        #pragma unroll
        for (int i = 0; i < 4; ++i) {
            s[i] += __shfl_xor_sync(0xffffffffu, s[i], 1);
            s[i] += __shfl_xor_sync(0xffffffffu, s[i], 2);
            q[i] += __shfl_xor_sync(0xffffffffu, q[i], 1);
            q[i] += __shfl_xor_sync(0xffffffffu, q[i], 2);
        }
        if ((lane & 3) == 0) {
            #pragma unroll
            for (int i = 0; i < 4; ++i) {
                int r = m0 + qr + ((i & 1) ? 8 : 0) + ((i >> 1) ? 16 : 0);
                psum[r * 4 + nw] = s[i];
                psq [r * 4 + nw] = q[i];
            }
        }
    }
    __syncthreads();
    if (tid < MTILE) {
        float S = psum[tid*4] + psum[tid*4+1] + psum[tid*4+2] + psum[tid*4+3];
        float Q = psq [tid*4] + psq [tid*4+1] + psq [tid*4+2] + psq [tid*4+3];
        float mu = S * (1.0f / H2);
        mu_s[tid] = mu;
        rs_s[tid] = rsqrtf(Q * (1.0f / H2) - mu * mu + 1e-5f);
    }
    __syncthreads();
    {
        int rows[4];
        float muv[4], rsv[4], dotp[4] = {0,0,0,0};
        #pragma unroll
        for (int i = 0; i < 4; ++i) {
            rows[i] = m0 + qr + ((i & 1) ? 8 : 0) + ((i >> 1) ? 16 : 0);
            muv[i] = mu_s[rows[i]];
            rsv[i] = rs_s[rows[i]];
        }
        #pragma unroll
        for (int mi = 0; mi < 2; ++mi)
            #pragma unroll
            for (int ni = 0; ni < 2; ++ni) {
                int cc = nw * 16 + ni * 8 + qc;
                float2 gv = *(const float2*)(g2 + cc);
                float2 bev = *(const float2*)(be2 + cc);
                float2 wv = *(const float2*)(W3 + cc);
                #pragma unroll
                for (int half = 0; half < 2; ++half) {
                    int i = mi * 2 + half, r = rows[i];
                    float2 idv = *(const float2*)(idbf + r * 64 + cc);
                    float y0 = (ac2[mi][ni][half*2]   - muv[i]) * rsv[i] * gv.x + bev.x;
                    float y1 = (ac2[mi][ni][half*2+1] - muv[i]) * rsv[i] * gv.y + bev.y;
                    float h0 = gelu_exact(y0 + idv.x);
                    float h1 = gelu_exact(y1 + idv.y);
                    dotp[i] += h0 * wv.x + h1 * wv.y;
                }
            }
        #pragma unroll
        for (int i = 0; i < 4; ++i) {
            dotp[i] += __shfl_xor_sync(0xffffffffu, dotp[i], 1);
            dotp[i] += __shfl_xor_sync(0xffffffffu, dotp[i], 2);
        }
        __syncthreads();
        if ((lane & 3) == 0) {
            #pragma unroll
            for (int i = 0; i < 4; ++i)
                psum[rows[i] * 4 + nw] = dotp[i];
        }
    }
    __syncthreads();
    if (tid < MTILE && (e0 + tid) < E) {
        out[e0 + tid] = psum[tid*4] + psum[tid*4+1] + psum[tid*4+2] + psum[tid*4+3]
                        + b3[0];
    }
}

extern "C" void kernel_launch(void* const* d_in, const int* in_sizes, int n_in,
                              void* d_out, int out_size) {
    const float* drug = (const float*)d_in[0];
    const float* dis  = (const float*)d_in[1];
    const int*   src  = (const int*)  d_in[2];
    const int*   dst  = (const int*)  d_in[3];
    const float* W1   = (const float*)d_in[4];
    const float* b1   = (const float*)d_in[5];
    const float* g1   = (const float*)d_in[6];
    const float* be1  = (const float*)d_in[7];
    const float* W2   = (const float*)d_in[8];
    const float* b2   = (const float*)d_in[9];
    const float* g2   = (const float*)d_in[10];
    const float* be2  = (const float*)d_in[11];
    const float* W3   = (const float*)d_in[12];
    const float* b3   = (const float*)d_in[13];
    const float* Ws   = (const float*)d_in[14];
    const float* bs   = (const float*)d_in[15];
    const int E = in_sizes[2];

    prep_weights<<<(NC1 * KDIM + H2 * H + 255) / 256, 256>>>(W1, Ws, W2);

    cudaFuncSetAttribute(mlp_hmma_kernel,
                         cudaFuncAttributeMaxDynamicSharedMemorySize, SMEM_BYTES);
    const int grid = (E + MTILE - 1) / MTILE;
    mlp_hmma_kernel<<<grid, THREADS, SMEM_BYTES>>>(
        drug, dis, src, dst, b1, g1, be1, b2, g2, be2, W3, b3, bs,
        (float*)d_out, E);
}